// round 11
// baseline (speedup 1.0000x reference)
#include <cuda_runtime.h>
#include <cuda_fp16.h>
#include <cstdint>
#include <cstddef>

#define B_ 4
#define T_ 2048
#define D_ 1024

// ---------------------------------------------------------------------------
// Scratch (__device__ globals: allocation-free rule)
// ---------------------------------------------------------------------------
__device__ __half g_xh[(size_t)B_ * T_ * D_];           // x in fp16
__device__ __half g_wt[3][(size_t)D_ * D_];             // W^T fp16 (q,k,v)
__device__ __half g_qkv[3][(size_t)B_ * T_ * D_];       // q,k,v fp16
__device__ __half g_vt[(size_t)B_ * D_ * T_];           // v^T fp16
__device__ __half g_p [(size_t)B_ * T_ * T_];           // E = exp(S) fp16
__device__ float  g_rs[(size_t)B_ * T_];                // row sums of E
__device__ int    g_cnt[64];                            // QK-tile counters [z][by]

constexpr size_t TD = (size_t)T_ * D_;
constexpr size_t TT = (size_t)T_ * T_;

#define CP_ASYNC16(dst, src) \
    asm volatile("cp.async.cg.shared.global [%0], [%1], 16;" :: "r"(dst), "l"(src) : "memory")
#define CP_COMMIT()  asm volatile("cp.async.commit_group;" ::: "memory")
#define CP_WAIT1()   asm volatile("cp.async.wait_group 1;" ::: "memory")
#define CP_WAIT0()   asm volatile("cp.async.wait_group 0;" ::: "memory")

__device__ __forceinline__ uint32_t smem_u32(const void* p) {
    uint32_t a;
    asm("{ .reg .u64 t; cvta.to.shared.u64 t, %1; cvt.u32.u64 %0, t; }" : "=r"(a) : "l"(p));
    return a;
}

#define LDSM_X4(r0, r1, r2, r3, addr)                                        \
    asm volatile("ldmatrix.sync.aligned.m8n8.x4.shared.b16 {%0,%1,%2,%3}, [%4];" \
        : "=r"(r0), "=r"(r1), "=r"(r2), "=r"(r3) : "r"(addr))

// m16n8k16 fp16 mma, fp32 accum
__device__ __forceinline__ void mma_f16(
    float& c0, float& c1, float& c2, float& c3,
    uint32_t a0, uint32_t a1, uint32_t a2, uint32_t a3,
    uint32_t b0, uint32_t b1)
{
    asm volatile(
        "mma.sync.aligned.m16n8k16.row.col.f32.f16.f16.f32 "
        "{%0,%1,%2,%3}, {%4,%5,%6,%7}, {%8,%9}, {%0,%1,%2,%3};"
        : "+f"(c0), "+f"(c1), "+f"(c2), "+f"(c3)
        : "r"(a0), "r"(a1), "r"(a2), "r"(a3), "r"(b0), "r"(b1));
}

// ---------------------------------------------------------------------------
// Core fp16 tensor GEMM tile (R7-proven config):
// C[128,128] tile of A[M,K] @ B[N,K]^T; 256 threads, 8 warps (2m x 4n),
// 64x32 warp tiles, smem rows 144B (conflict-free LDSM), 3-stage cp.async.
// ---------------------------------------------------------------------------
constexpr int BM = 128, BN = 128, BK = 64;
constexpr int LDHB = 144;                      // bytes per smem row
constexpr int TILE_BYTES  = BM * LDHB;         // 18432
constexpr int STAGE_BYTES = 2 * TILE_BYTES;    // 36864 (A + B)
constexpr int NSTAGE = 3;
constexpr int SMEM_BYTES = NSTAGE * STAGE_BYTES;  // 110592

template <bool BIAS, bool EXPO, bool DIVRS, bool OUTH>
__device__ __forceinline__ void gemm_core(
    const __half* __restrict__ Ag,   // &A[m0 * K]
    const __half* __restrict__ Bg,   // &B[n0 * K]
    const float* __restrict__ bias,
    void* __restrict__ Cv,           // batch-offset C
    float* __restrict__ rsz,         // batch-offset rs (EXPO: atomic, DIVRS: read)
    int N, int K, int KT, int m0, int n0, float scale, bool diag)
{
    extern __shared__ char sm[];
    const uint32_t sm_b = smem_u32(sm);

    const int tid = threadIdx.x;
    const int wid = tid >> 5;
    const int lid = tid & 31;
    const int wm = wid >> 2;                   // 0..1
    const int wn = wid & 3;                    // 0..3
    const int g  = lid >> 2;                   // 0..7
    const int t4 = lid & 3;                    // 0..3

    auto load_stage = [&](int stage, int kt) {
        const uint32_t ab = sm_b + stage * STAGE_BYTES;
        const uint32_t bbs = ab + TILE_BYTES;
        const __half* Asrc = Ag + (size_t)kt * BK;
        const __half* Bsrc = Bg + (size_t)kt * BK;
#pragma unroll
        for (int i = 0; i < 4; i++) {
            int idx = i * 256 + tid;           // 0..1023
            int row = idx >> 3, c = idx & 7;
            uint32_t off = (uint32_t)(row * LDHB + c * 16);
            CP_ASYNC16(ab + off,  Asrc + (size_t)row * K + c * 8);
            CP_ASYNC16(bbs + off, Bsrc + (size_t)row * K + c * 8);
        }
    };

    load_stage(0, 0);
    CP_COMMIT();
    if (KT > 1) { load_stage(1, 1); CP_COMMIT(); }

    const int fr = lid & 15;
    const uint32_t lk = (lid & 16) ? 16u : 0u;
    const uint32_t aoff = (uint32_t)((wm * 64 + fr) * LDHB) + lk;
    const uint32_t boff = (uint32_t)(TILE_BYTES + (wn * 32 + fr) * LDHB) + lk;

    float acc[4][4][4];
#pragma unroll
    for (int i = 0; i < 4; i++)
#pragma unroll
        for (int j = 0; j < 4; j++)
#pragma unroll
            for (int r = 0; r < 4; r++) acc[i][j][r] = 0.f;

    int stage = 0;
    for (int kt = 0; kt < KT; kt++) {
        if (kt + 1 < KT) CP_WAIT1(); else CP_WAIT0();
        __syncthreads();

        if (kt + 2 < KT) {
            int ns = stage + 2; if (ns >= NSTAGE) ns -= NSTAGE;
            load_stage(ns, kt + 2);
            CP_COMMIT();
        }

        const uint32_t Sb = sm_b + stage * STAGE_BYTES;

#pragma unroll
        for (int s = 0; s < 4; s++) {          // 4 x k16 steps
            uint32_t a[4][4], b[2][4];
#pragma unroll
            for (int mt = 0; mt < 4; mt++)
                LDSM_X4(a[mt][0], a[mt][1], a[mt][2], a[mt][3],
                        Sb + aoff + mt * (16 * LDHB) + s * 32);
#pragma unroll
            for (int p = 0; p < 2; p++)
                LDSM_X4(b[p][0], b[p][1], b[p][2], b[p][3],
                        Sb + boff + p * (16 * LDHB) + s * 32);
#pragma unroll
            for (int mt = 0; mt < 4; mt++)
#pragma unroll
                for (int nt = 0; nt < 4; nt++) {
                    const int p = nt >> 1, o = nt & 1;
                    mma_f16(acc[mt][nt][0], acc[mt][nt][1],
                            acc[mt][nt][2], acc[mt][nt][3],
                            a[mt][0], a[mt][1], a[mt][2], a[mt][3],
                            b[p][o], b[p][2 + o]);
                }
        }
        stage++; if (stage >= NSTAGE) stage = 0;
    }

    // Epilogue: c0,c1 -> (row g, cols 2t4,2t4+1); c2,c3 -> row g+8.
#pragma unroll
    for (int mt = 0; mt < 4; mt++) {
        const int mr = m0 + wm * 64 + mt * 16 + g;
        float rsum0 = 0.f, rsum1 = 0.f;
        float ia = 1.f, ib = 1.f;
        if (DIVRS) {
            ia = 1.0f / __ldg(rsz + mr);
            ib = 1.0f / __ldg(rsz + mr + 8);
        }
#pragma unroll
        for (int nt = 0; nt < 4; nt++) {
            const int nc = n0 + wn * 32 + nt * 8 + 2 * t4;
            float f0 = acc[mt][nt][0], f1 = acc[mt][nt][1];
            float f2 = acc[mt][nt][2], f3 = acc[mt][nt][3];
            if (BIAS) {
                float b0 = __ldg(bias + nc), b1 = __ldg(bias + nc + 1);
                f0 += b0; f1 += b1; f2 += b0; f3 += b1;
            }
            if (EXPO) {
                float e0 = __expf(f0 * scale), e1 = __expf(f1 * scale);
                float e2 = __expf(f2 * scale), e3 = __expf(f3 * scale);
                if (diag) {
                    if (nc     > mr    ) e0 = 0.f;
                    if (nc + 1 > mr    ) e1 = 0.f;
                    if (nc     > mr + 8) e2 = 0.f;
                    if (nc + 1 > mr + 8) e3 = 0.f;
                }
                __half2 h0 = __floats2half2_rn(e0, e1);
                __half2 h1 = __floats2half2_rn(e2, e3);
                float2 r0 = __half22float2(h0), r1 = __half22float2(h1);
                rsum0 += r0.x + r0.y;
                rsum1 += r1.x + r1.y;
                __half* C = (__half*)Cv;
                *(__half2*)(C + (size_t)mr * N + nc)       = h0;
                *(__half2*)(C + (size_t)(mr + 8) * N + nc) = h1;
            } else if (OUTH) {
                __half* C = (__half*)Cv;
                *(__half2*)(C + (size_t)mr * N + nc)       = __floats2half2_rn(f0, f1);
                *(__half2*)(C + (size_t)(mr + 8) * N + nc) = __floats2half2_rn(f2, f3);
            } else {
                if (DIVRS) { f0 *= ia; f1 *= ia; f2 *= ib; f3 *= ib; }
                float* C = (float*)Cv;
                *(float2*)(C + (size_t)mr * N + nc)       = make_float2(f0, f1);
                *(float2*)(C + (size_t)(mr + 8) * N + nc) = make_float2(f2, f3);
            }
        }
        if (EXPO) {
            rsum0 += __shfl_xor_sync(0xffffffffu, rsum0, 1);
            rsum0 += __shfl_xor_sync(0xffffffffu, rsum0, 2);
            rsum1 += __shfl_xor_sync(0xffffffffu, rsum1, 1);
            rsum1 += __shfl_xor_sync(0xffffffffu, rsum1, 2);
            if (t4 == 0) {
                atomicAdd(rsz + mr,     rsum0);
                atomicAdd(rsz + mr + 8, rsum1);
            }
        }
    }
}

// ---------------------------------------------------------------------------
// QKV projection kernel (grid: D/BN x M/BM x 3)
// ---------------------------------------------------------------------------
__global__ __launch_bounds__(256, 2) void qkv_kernel(
    const __half* __restrict__ xh, const __half* __restrict__ wt,
    const float* __restrict__ bq, const float* __restrict__ bk,
    const float* __restrict__ bv, __half* __restrict__ qkv)
{
    const int z = blockIdx.z;
    const int m0 = blockIdx.y * BM, n0 = blockIdx.x * BN;
    const float* bias = (z == 0) ? bq : (z == 1) ? bk : bv;
    gemm_core<true, false, false, true>(
        xh + (size_t)m0 * D_,
        wt + (size_t)z * D_ * D_ + (size_t)n0 * D_,
        bias, qkv + (size_t)z * ((size_t)B_ * T_ * D_), nullptr,
        D_, D_, D_ / BK, m0, n0, 1.f, false);
}

// ---------------------------------------------------------------------------
// Fused QK->exp->rowsum + PV kernel with device-side row dependencies.
// Grid: [544 QK tiles (rows 15..0, all z), 512 PV tiles (heavy rows first)].
// QK tile completion bumps cnt[z][by]; PV tile spins until cnt == by+1.
// Deadlock-free: CTAs schedule in bid order, so every QK tile is
// running-or-done before any PV CTA occupies a slot.
// ---------------------------------------------------------------------------
constexpr int NQK = 136 * 4;   // lower-triangle tiles x batches

__global__ __launch_bounds__(256, 2) void attn_kernel(
    const __half* __restrict__ q, const __half* __restrict__ k,
    const __half* __restrict__ vt, __half* __restrict__ E,
    float* __restrict__ out, float* __restrict__ rs, int* __restrict__ cnt)
{
    const int idx = blockIdx.x;
    if (idx < NQK) {
        const int z = idx & 3;
        int rem = idx >> 2;                 // 0..135, rows descending
        int by = 15;
        while (rem >= by + 1) { rem -= by + 1; by--; }
        const int bx = rem;
        const int m0 = by * BM, n0 = bx * BN;
        gemm_core<false, true, false, true>(
            q + (size_t)z * TD + (size_t)m0 * D_,
            k + (size_t)z * TD + (size_t)n0 * D_,
            nullptr, E + (size_t)z * TT, rs + (size_t)z * T_,
            T_, D_, D_ / BK, m0, n0, 1.0f / 32.0f, by == bx);
        __threadfence();
        __syncthreads();
        if (threadIdx.x == 0) atomicAdd(cnt + z * 16 + by, 1);
    } else {
        const int p = idx - NQK;
        const int d = p >> 5, sub = p & 31;
        const int by = 15 - d;              // heavy rows first
        const int z = sub >> 3, bxd = sub & 7;
        const int need = by + 1;
        if (threadIdx.x == 0) {
            volatile int* cp = cnt + z * 16 + by;
            while (*cp < need) __nanosleep(64);
        }
        __syncthreads();
        __threadfence();
        const int m0 = by * BM, n0 = bxd * BN;
        gemm_core<false, false, true, false>(
            E + (size_t)z * TT + (size_t)m0 * T_,
            vt + (size_t)z * TD + (size_t)n0 * T_,
            nullptr, out + (size_t)z * TD, rs + (size_t)z * T_,
            D_, T_, (by + 1) * 2, m0, n0, 1.f, false);
    }
}

// ---------------------------------------------------------------------------
// fp32 -> fp16 convert (x)
// ---------------------------------------------------------------------------
__global__ void f2h_kernel(const float* __restrict__ src, __half* __restrict__ dst, int n8)
{
    int i = blockIdx.x * blockDim.x + threadIdx.x;
    if (i >= n8) return;
    float4 v0 = ((const float4*)src)[2 * i];
    float4 v1 = ((const float4*)src)[2 * i + 1];
    __half2 h[4];
    h[0] = __floats2half2_rn(v0.x, v0.y);
    h[1] = __floats2half2_rn(v0.z, v0.w);
    h[2] = __floats2half2_rn(v1.x, v1.y);
    h[3] = __floats2half2_rn(v1.z, v1.w);
    ((uint4*)dst)[i] = *(uint4*)h;
}

// ---------------------------------------------------------------------------
// Zero the row-sum accumulator and tile counters
// ---------------------------------------------------------------------------
__global__ void zero_rs_kernel(float* __restrict__ rs, int* __restrict__ cnt, int n)
{
    int i = blockIdx.x * blockDim.x + threadIdx.x;
    if (i < n) rs[i] = 0.f;
    if (i < 64) cnt[i] = 0;
}

// ---------------------------------------------------------------------------
// Transpose fp32 -> fp16 for the three weight matrices (z selects q/k/v)
// ---------------------------------------------------------------------------
__global__ void transpose_f2h3(const float* __restrict__ W0, const float* __restrict__ W1,
                               const float* __restrict__ W2, __half* __restrict__ dst,
                               int R, int Ccols, size_t sDst)
{
    const float* src = (blockIdx.z == 0) ? W0 : (blockIdx.z == 1) ? W1 : W2;
    __half* d = dst + (size_t)blockIdx.z * sDst;
    __shared__ float t[32][33];
    const int r0 = blockIdx.y * 32, c0 = blockIdx.x * 32;
#pragma unroll
    for (int i = 0; i < 4; i++) {
        int r = r0 + threadIdx.y + i * 8;
        t[threadIdx.y + i * 8][threadIdx.x] = src[(size_t)r * Ccols + c0 + threadIdx.x];
    }
    __syncthreads();
#pragma unroll
    for (int i = 0; i < 4; i++) {
        int c = c0 + threadIdx.y + i * 8;
        d[(size_t)c * R + r0 + threadIdx.x] =
            __float2half_rn(t[threadIdx.x][threadIdx.y + i * 8]);
    }
}

// ---------------------------------------------------------------------------
// Transpose fp16 -> fp16: dst[c, r] = src[r, c]; batched via blockIdx.z
// ---------------------------------------------------------------------------
__global__ void transpose_h2h(const __half* __restrict__ src, __half* __restrict__ dst,
                              int R, int Ccols, size_t sSrc, size_t sDst)
{
    src += (size_t)blockIdx.z * sSrc;
    dst += (size_t)blockIdx.z * sDst;
    __shared__ __half t[32][34];
    const int r0 = blockIdx.y * 32, c0 = blockIdx.x * 32;
#pragma unroll
    for (int i = 0; i < 4; i++) {
        int r = r0 + threadIdx.y + i * 8;
        t[threadIdx.y + i * 8][threadIdx.x] = src[(size_t)r * Ccols + c0 + threadIdx.x];
    }
    __syncthreads();
#pragma unroll
    for (int i = 0; i < 4; i++) {
        int c = c0 + threadIdx.y + i * 8;
        dst[(size_t)c * R + r0 + threadIdx.x] = t[threadIdx.x][threadIdx.y + i * 8];
    }
}

// ---------------------------------------------------------------------------
extern "C" void kernel_launch(void* const* d_in, const int* in_sizes, int n_in,
                              void* d_out, int out_size)
{
    const float* x  = (const float*)d_in[0];
    const float* Wq = (const float*)d_in[1];
    const float* bq = (const float*)d_in[2];
    const float* Wk = (const float*)d_in[3];
    const float* bk = (const float*)d_in[4];
    const float* Wv = (const float*)d_in[5];
    const float* bv = (const float*)d_in[6];
    float* out = (float*)d_out;

    __half *xh, *wt, *qkv, *vt, *p;
    float *rs;
    int *cnt;
    cudaGetSymbolAddress((void**)&xh,  g_xh);
    cudaGetSymbolAddress((void**)&wt,  g_wt);
    cudaGetSymbolAddress((void**)&qkv, g_qkv);
    cudaGetSymbolAddress((void**)&vt,  g_vt);
    cudaGetSymbolAddress((void**)&p,   g_p);
    cudaGetSymbolAddress((void**)&rs,  g_rs);
    cudaGetSymbolAddress((void**)&cnt, g_cnt);

    const int M = B_ * T_;               // 8192
    const size_t DD = (size_t)D_ * D_;
    __half* q = qkv;
    __half* k = qkv + (size_t)M * D_;
    __half* v = qkv + 2 * (size_t)M * D_;

    cudaFuncSetAttribute(qkv_kernel,  cudaFuncAttributeMaxDynamicSharedMemorySize, SMEM_BYTES);
    cudaFuncSetAttribute(attn_kernel, cudaFuncAttributeMaxDynamicSharedMemorySize, SMEM_BYTES);

    // 0) x -> fp16; zero rs + counters; W -> W^T fp16
    f2h_kernel<<<(M * D_ / 8 + 255) / 256, 256>>>(x, xh, M * D_ / 8);
    zero_rs_kernel<<<(B_ * T_ + 255) / 256, 256>>>(rs, cnt, B_ * T_);
    transpose_f2h3<<<dim3(D_ / 32, D_ / 32, 3), dim3(32, 8)>>>(Wq, Wk, Wv, wt, D_, D_, DD);

    // 1) fused QKV projections
    dim3 gProj(D_ / BN, M / BM, 3);
    qkv_kernel<<<gProj, 256, SMEM_BYTES>>>(xh, wt, bq, bk, bv, qkv);

    // 2) v^T (per batch), fp16
    transpose_h2h<<<dim3(D_ / 32, T_ / 32, B_), dim3(32, 8)>>>(v, vt, T_, D_, TD, TD);

    // 3+4) fused QK->exp->rowsum + PV with device-side row dependencies
    attn_kernel<<<NQK + 512, 256, SMEM_BYTES>>>(q, k, vt, p, out, rs, cnt);
}

// round 12
// speedup vs baseline: 1.4086x; 1.4086x over previous
#include <cuda_runtime.h>
#include <cuda_fp16.h>
#include <cstdint>
#include <cstddef>

#define B_ 4
#define T_ 2048
#define D_ 1024

// ---------------------------------------------------------------------------
// Scratch (__device__ globals: allocation-free rule)
// ---------------------------------------------------------------------------
__device__ __half g_xh[(size_t)B_ * T_ * D_];           // x in fp16
__device__ __half g_wt[3][(size_t)D_ * D_];             // W^T fp16 (q,k,v)
__device__ __half g_qkv[3][(size_t)B_ * T_ * D_];       // q,k,v fp16
__device__ __half g_p [(size_t)B_ * T_ * T_];           // E = exp(S) fp16
__device__ float  g_rs[(size_t)B_ * T_];                // row sums of E

#define CP_ASYNC16(dst, src) \
    asm volatile("cp.async.cg.shared.global [%0], [%1], 16;" :: "r"(dst), "l"(src) : "memory")
#define CP_COMMIT()  asm volatile("cp.async.commit_group;" ::: "memory")
#define CP_WAIT1()   asm volatile("cp.async.wait_group 1;" ::: "memory")
#define CP_WAIT0()   asm volatile("cp.async.wait_group 0;" ::: "memory")

__device__ __forceinline__ uint32_t smem_u32(const void* p) {
    uint32_t a;
    asm("{ .reg .u64 t; cvta.to.shared.u64 t, %1; cvt.u32.u64 %0, t; }" : "=r"(a) : "l"(p));
    return a;
}

#define LDSM_X4(r0, r1, r2, r3, addr)                                        \
    asm volatile("ldmatrix.sync.aligned.m8n8.x4.shared.b16 {%0,%1,%2,%3}, [%4];" \
        : "=r"(r0), "=r"(r1), "=r"(r2), "=r"(r3) : "r"(addr))

#define LDSM_X4T(r0, r1, r2, r3, addr)                                       \
    asm volatile("ldmatrix.sync.aligned.m8n8.x4.trans.shared.b16 {%0,%1,%2,%3}, [%4];" \
        : "=r"(r0), "=r"(r1), "=r"(r2), "=r"(r3) : "r"(addr))

// m16n8k16 fp16 mma, fp32 accum
__device__ __forceinline__ void mma_f16(
    float& c0, float& c1, float& c2, float& c3,
    uint32_t a0, uint32_t a1, uint32_t a2, uint32_t a3,
    uint32_t b0, uint32_t b1)
{
    asm volatile(
        "mma.sync.aligned.m16n8k16.row.col.f32.f16.f16.f32 "
        "{%0,%1,%2,%3}, {%4,%5,%6,%7}, {%8,%9}, {%0,%1,%2,%3};"
        : "+f"(c0), "+f"(c1), "+f"(c2), "+f"(c3)
        : "r"(a0), "r"(a1), "r"(a2), "r"(a3), "r"(b0), "r"(b1));
}

// ---------------------------------------------------------------------------
// fp16 tensor GEMM (R7-proven): C[M,N] = A[M,K] @ Bm[N,K]^T.
// 128x128x64 block tile, 8 warps (2m x 4n) -> 64x32 warp tiles, 256 threads.
// A smem rows 144B; 3-stage cp.async; 2 CTAs/SM.
// TRV: B operand is V[t,d] (row-major over t); tile stored [64 s x 128 d]
//      with 272B rows and consumed via ldmatrix.trans (B = V^T implicitly).
// EXPO: epilogue exp(acc*scale), causal mask on diag tile, rowsum atomics.
// DIVRS: divide by rs[row]. KLIM: causal K clip (heavy-first m order).
// CSKIP: skip fully-masked tiles.
// ---------------------------------------------------------------------------
constexpr int BM = 128, BN = 128, BK = 64;
constexpr int LDHB = 144;                      // A/B(K-major) smem row bytes
constexpr int LDVB = 272;                      // TRV B smem row bytes (128 d)
constexpr int TILE_BYTES  = BM * LDHB;         // 18432
constexpr int STAGE_BYTES = 2 * TILE_BYTES;    // 36864 (TRV B fits: 64*272=17408)
constexpr int NSTAGE = 3;
constexpr int SMEM_BYTES = NSTAGE * STAGE_BYTES;  // 110592

template <bool QKV3, bool BIAS, bool EXPO, bool DIVRS, bool CSKIP, bool KLIM, bool OUTH, bool TRV>
__global__ __launch_bounds__(256, 2) void gemm_h(
    const __half* __restrict__ A, const __half* __restrict__ Bm,
    const float* __restrict__ bias0, const float* __restrict__ bias1,
    const float* __restrict__ bias2, void* __restrict__ Cv,
    float* __restrict__ rs,
    int M, int N, int K, float scale, size_t sA, size_t sB, size_t sC)
{
    const int by = KLIM ? ((int)gridDim.y - 1 - (int)blockIdx.y) : (int)blockIdx.y;
    const int m0 = by * BM;
    const int n0 = blockIdx.x * BN;
    if (CSKIP && n0 >= m0 + BM) return;        // fully above causal diagonal

    const int z = blockIdx.z;
    A  += QKV3 ? 0 : (size_t)z * sA;
    Bm += (size_t)z * sB;
    const float* bias = bias0;
    if (QKV3) bias = (z == 0) ? bias0 : (z == 1) ? bias1 : bias2;

    int Keff = K;
    if (KLIM) { int lim = m0 + BM; Keff = lim < K ? lim : K; }
    const int KT = Keff / BK;

    extern __shared__ char sm[];
    const uint32_t sm_b = smem_u32(sm);

    const int tid = threadIdx.x;
    const int wid = tid >> 5;
    const int lid = tid & 31;
    const int wm = wid >> 2;                   // 0..1
    const int wn = wid & 3;                    // 0..3
    const int g  = lid >> 2;                   // 0..7
    const int t4 = lid & 3;                    // 0..3

    const __half* Ag = A + (size_t)m0 * K;
    const __half* Bg = TRV ? Bm : Bm + (size_t)n0 * K;

    // Stage loader: A 128x64h + B (K-major 128x64h | TRV 64s x 128d)
    auto load_stage = [&](int stage, int kt) {
        const uint32_t ab = sm_b + stage * STAGE_BYTES;
        const uint32_t bbs = ab + TILE_BYTES;
        const __half* Asrc = Ag + (size_t)kt * BK;
#pragma unroll
        for (int i = 0; i < 4; i++) {
            int idx = i * 256 + tid;           // 0..1023
            int row = idx >> 3, c = idx & 7;
            CP_ASYNC16(ab + (uint32_t)(row * LDHB + c * 16),
                       Asrc + (size_t)row * K + c * 8);
        }
        if (TRV) {
            // V tile: rows s = kt*64 + r (stride D_), cols n0..n0+127
#pragma unroll
            for (int i = 0; i < 4; i++) {
                int idx = i * 256 + tid;       // 0..1023
                int r = idx >> 4, c = idx & 15;
                CP_ASYNC16(bbs + (uint32_t)(r * LDVB + c * 16),
                           Bg + (size_t)(kt * BK + r) * D_ + n0 + c * 8);
            }
        } else {
            const __half* Bsrc = Bg + (size_t)kt * BK;
#pragma unroll
            for (int i = 0; i < 4; i++) {
                int idx = i * 256 + tid;
                int row = idx >> 3, c = idx & 7;
                CP_ASYNC16(bbs + (uint32_t)(row * LDHB + c * 16),
                           Bsrc + (size_t)row * K + c * 8);
            }
        }
    };

    load_stage(0, 0);
    CP_COMMIT();
    if (KT > 1) { load_stage(1, 1); CP_COMMIT(); }

    // LDSM per-lane addresses.
    const int fr = lid & 15;
    const uint32_t lk = (lid & 16) ? 16u : 0u;
    const uint32_t aoff = (uint32_t)((wm * 64 + fr) * LDHB) + lk;
    // K-major B path:
    const uint32_t boff = (uint32_t)(TILE_BYTES + (wn * 32 + fr) * LDHB) + lk;
    // TRV path: lanes grouped 8; m0..m3 = {n0-7,k0-7},{n8-15,k0-7},{n0-7,k8-15},{n8-15,k8-15}
    const int i8 = lid & 7;
    const int grp = lid >> 3;
    const uint32_t btrv = (uint32_t)(TILE_BYTES
                          + (((grp & 2) ? 8 : 0) + i8) * LDVB
                          + (wn * 32 + ((grp & 1) ? 8 : 0)) * 2);

    float acc[4][4][4];
#pragma unroll
    for (int i = 0; i < 4; i++)
#pragma unroll
        for (int j = 0; j < 4; j++)
#pragma unroll
            for (int r = 0; r < 4; r++) acc[i][j][r] = 0.f;

    int stage = 0;
    for (int kt = 0; kt < KT; kt++) {
        if (kt + 1 < KT) CP_WAIT1(); else CP_WAIT0();
        __syncthreads();

        if (kt + 2 < KT) {
            int ns = stage + 2; if (ns >= NSTAGE) ns -= NSTAGE;
            load_stage(ns, kt + 2);
            CP_COMMIT();
        }

        const uint32_t Sb = sm_b + stage * STAGE_BYTES;

#pragma unroll
        for (int s = 0; s < 4; s++) {          // 4 x k16 steps
            uint32_t a[4][4], b[2][4];
#pragma unroll
            for (int mt = 0; mt < 4; mt++)
                LDSM_X4(a[mt][0], a[mt][1], a[mt][2], a[mt][3],
                        Sb + aoff + mt * (16 * LDHB) + s * 32);
            if (TRV) {
#pragma unroll
                for (int p = 0; p < 2; p++)
                    LDSM_X4T(b[p][0], b[p][1], b[p][2], b[p][3],
                             Sb + btrv + s * (16 * LDVB) + p * 32);
            } else {
#pragma unroll
                for (int p = 0; p < 2; p++)
                    LDSM_X4(b[p][0], b[p][1], b[p][2], b[p][3],
                            Sb + boff + p * (16 * LDHB) + s * 32);
            }
#pragma unroll
            for (int mt = 0; mt < 4; mt++)
#pragma unroll
                for (int nt = 0; nt < 4; nt++) {
                    const int p = nt >> 1, o = nt & 1;
                    mma_f16(acc[mt][nt][0], acc[mt][nt][1],
                            acc[mt][nt][2], acc[mt][nt][3],
                            a[mt][0], a[mt][1], a[mt][2], a[mt][3],
                            b[p][o], b[p][2 + o]);
                }
        }
        stage++; if (stage >= NSTAGE) stage = 0;
    }

    const bool diag = EXPO && (m0 == n0);

    // Epilogue: c0,c1 -> (row g, cols 2t4,2t4+1); c2,c3 -> row g+8.
#pragma unroll
    for (int mt = 0; mt < 4; mt++) {
        const int mr = m0 + wm * 64 + mt * 16 + g;
        float rsum0 = 0.f, rsum1 = 0.f;
        float ia = 1.f, ib = 1.f;
        if (DIVRS) {
            ia = 1.0f / __ldg(rs + (size_t)z * T_ + mr);
            ib = 1.0f / __ldg(rs + (size_t)z * T_ + mr + 8);
        }
#pragma unroll
        for (int nt = 0; nt < 4; nt++) {
            const int nc = n0 + wn * 32 + nt * 8 + 2 * t4;
            float f0 = acc[mt][nt][0], f1 = acc[mt][nt][1];
            float f2 = acc[mt][nt][2], f3 = acc[mt][nt][3];
            if (BIAS) {
                float b0 = __ldg(bias + nc), b1 = __ldg(bias + nc + 1);
                f0 += b0; f1 += b1; f2 += b0; f3 += b1;
            }
            if (EXPO) {
                float e0 = __expf(f0 * scale), e1 = __expf(f1 * scale);
                float e2 = __expf(f2 * scale), e3 = __expf(f3 * scale);
                if (diag) {
                    if (nc     > mr    ) e0 = 0.f;
                    if (nc + 1 > mr    ) e1 = 0.f;
                    if (nc     > mr + 8) e2 = 0.f;
                    if (nc + 1 > mr + 8) e3 = 0.f;
                }
                __half2 h0 = __floats2half2_rn(e0, e1);
                __half2 h1 = __floats2half2_rn(e2, e3);
                float2 r0 = __half22float2(h0), r1 = __half22float2(h1);
                rsum0 += r0.x + r0.y;
                rsum1 += r1.x + r1.y;
                __half* C = (__half*)Cv + (size_t)z * sC;
                *(__half2*)(C + (size_t)mr * N + nc)       = h0;
                *(__half2*)(C + (size_t)(mr + 8) * N + nc) = h1;
            } else if (OUTH) {
                __half* C = (__half*)Cv + (size_t)z * sC;
                *(__half2*)(C + (size_t)mr * N + nc)       = __floats2half2_rn(f0, f1);
                *(__half2*)(C + (size_t)(mr + 8) * N + nc) = __floats2half2_rn(f2, f3);
            } else {
                if (DIVRS) { f0 *= ia; f1 *= ia; f2 *= ib; f3 *= ib; }
                float* C = (float*)Cv + (size_t)z * sC;
                *(float2*)(C + (size_t)mr * N + nc)       = make_float2(f0, f1);
                *(float2*)(C + (size_t)(mr + 8) * N + nc) = make_float2(f2, f3);
            }
        }
        if (EXPO) {
            rsum0 += __shfl_xor_sync(0xffffffffu, rsum0, 1);
            rsum0 += __shfl_xor_sync(0xffffffffu, rsum0, 2);
            rsum1 += __shfl_xor_sync(0xffffffffu, rsum1, 1);
            rsum1 += __shfl_xor_sync(0xffffffffu, rsum1, 2);
            if (t4 == 0) {
                atomicAdd(rs + (size_t)z * T_ + mr,     rsum0);
                atomicAdd(rs + (size_t)z * T_ + mr + 8, rsum1);
            }
        }
    }
}

// ---------------------------------------------------------------------------
// fp32 -> fp16 convert (x)
// ---------------------------------------------------------------------------
__global__ void f2h_kernel(const float* __restrict__ src, __half* __restrict__ dst, int n8)
{
    int i = blockIdx.x * blockDim.x + threadIdx.x;
    if (i >= n8) return;
    float4 v0 = ((const float4*)src)[2 * i];
    float4 v1 = ((const float4*)src)[2 * i + 1];
    __half2 h[4];
    h[0] = __floats2half2_rn(v0.x, v0.y);
    h[1] = __floats2half2_rn(v0.z, v0.w);
    h[2] = __floats2half2_rn(v1.x, v1.y);
    h[3] = __floats2half2_rn(v1.z, v1.w);
    ((uint4*)dst)[i] = *(uint4*)h;
}

// ---------------------------------------------------------------------------
// Zero the row-sum accumulator
// ---------------------------------------------------------------------------
__global__ void zero_rs_kernel(float* __restrict__ rs, int n)
{
    int i = blockIdx.x * blockDim.x + threadIdx.x;
    if (i < n) rs[i] = 0.f;
}

// ---------------------------------------------------------------------------
// Transpose fp32 -> fp16 for the three weight matrices (z selects q/k/v)
// ---------------------------------------------------------------------------
__global__ void transpose_f2h3(const float* __restrict__ W0, const float* __restrict__ W1,
                               const float* __restrict__ W2, __half* __restrict__ dst,
                               int R, int Ccols, size_t sDst)
{
    const float* src = (blockIdx.z == 0) ? W0 : (blockIdx.z == 1) ? W1 : W2;
    __half* d = dst + (size_t)blockIdx.z * sDst;
    __shared__ float t[32][33];
    const int r0 = blockIdx.y * 32, c0 = blockIdx.x * 32;
#pragma unroll
    for (int i = 0; i < 4; i++) {
        int r = r0 + threadIdx.y + i * 8;
        t[threadIdx.y + i * 8][threadIdx.x] = src[(size_t)r * Ccols + c0 + threadIdx.x];
    }
    __syncthreads();
#pragma unroll
    for (int i = 0; i < 4; i++) {
        int c = c0 + threadIdx.y + i * 8;
        d[(size_t)c * R + r0 + threadIdx.x] =
            __float2half_rn(t[threadIdx.x][threadIdx.y + i * 8]);
    }
}

// ---------------------------------------------------------------------------
extern "C" void kernel_launch(void* const* d_in, const int* in_sizes, int n_in,
                              void* d_out, int out_size)
{
    const float* x  = (const float*)d_in[0];
    const float* Wq = (const float*)d_in[1];
    const float* bq = (const float*)d_in[2];
    const float* Wk = (const float*)d_in[3];
    const float* bk = (const float*)d_in[4];
    const float* Wv = (const float*)d_in[5];
    const float* bv = (const float*)d_in[6];
    float* out = (float*)d_out;

    __half *xh, *wt, *qkv, *p;
    float *rs;
    cudaGetSymbolAddress((void**)&xh,  g_xh);
    cudaGetSymbolAddress((void**)&wt,  g_wt);
    cudaGetSymbolAddress((void**)&qkv, g_qkv);
    cudaGetSymbolAddress((void**)&p,   g_p);
    cudaGetSymbolAddress((void**)&rs,  g_rs);

    const int M = B_ * T_;               // 8192
    const size_t TD = (size_t)T_ * D_;
    const size_t TT = (size_t)T_ * T_;
    const size_t DD = (size_t)D_ * D_;
    __half* q = qkv;
    __half* k = qkv + (size_t)M * D_;
    __half* v = qkv + 2 * (size_t)M * D_;

    cudaFuncSetAttribute(gemm_h<true,  true,  false, false, false, false, true,  false>, cudaFuncAttributeMaxDynamicSharedMemorySize, SMEM_BYTES);
    cudaFuncSetAttribute(gemm_h<false, false, true,  false, true,  false, true,  false>, cudaFuncAttributeMaxDynamicSharedMemorySize, SMEM_BYTES);
    cudaFuncSetAttribute(gemm_h<false, false, false, true,  false, true,  false, true >, cudaFuncAttributeMaxDynamicSharedMemorySize, SMEM_BYTES);

    // 0) x -> fp16; zero rs; W -> W^T fp16 (single launch)
    f2h_kernel<<<(M * D_ / 8 + 255) / 256, 256>>>(x, xh, M * D_ / 8);
    zero_rs_kernel<<<(B_ * T_ + 255) / 256, 256>>>(rs, B_ * T_);
    transpose_f2h3<<<dim3(D_ / 32, D_ / 32, 3), dim3(32, 8)>>>(Wq, Wk, Wv, wt, D_, D_, DD);

    // 1) fused QKV projections (one launch, z selects q/k/v), fp16 out
    dim3 gProj(D_ / BN, M / BM, 3);
    gemm_h<true, true, false, false, false, false, true, false><<<gProj, 256, SMEM_BYTES>>>(
        xh, wt, bq, bk, bv, qkv, nullptr, M, D_, D_, 1.f, 0, DD, (size_t)M * D_);

    // 2) E = exp(Q K^T / 32) fp16 (lower-triangle tiles only, diag masked),
    //    row sums accumulated into rs via atomics.
    dim3 gS(T_ / BN, T_ / BM, B_);
    gemm_h<false, false, true, false, true, false, true, false><<<gS, 256, SMEM_BYTES>>>(
        q, k, nullptr, nullptr, nullptr, p, rs, T_, T_, D_, 1.0f / 32.0f, TD, TD, TT);

    // 3) out = (E @ V) / rs, V consumed directly via ldmatrix.trans (no v^T),
    //    causal K-limit, heavy-first m order, fp32 out
    dim3 gPV(D_ / BN, T_ / BM, B_);
    gemm_h<false, false, false, true, false, true, false, true><<<gPV, 256, SMEM_BYTES>>>(
        p, v, nullptr, nullptr, nullptr, out, rs, T_, D_, T_, 1.f, TT, TD, TD);
}

// round 13
// speedup vs baseline: 1.4348x; 1.0186x over previous
#include <cuda_runtime.h>
#include <cuda_fp16.h>
#include <cstdint>
#include <cstddef>

#define B_ 4
#define T_ 2048
#define D_ 1024

// ---------------------------------------------------------------------------
// Scratch (__device__ globals: allocation-free rule)
// ---------------------------------------------------------------------------
__device__ __half g_xh[(size_t)B_ * T_ * D_];           // x in fp16
__device__ __half g_wt[3][(size_t)D_ * D_];             // W^T fp16 (q,k,v)
__device__ __half g_qkv[3][(size_t)B_ * T_ * D_];       // q,k,v fp16
__device__ __half g_p [(size_t)B_ * T_ * T_];           // E = exp(S) fp16
__device__ float  g_rs[(size_t)B_ * T_];                // row sums of E

#define CP_ASYNC16(dst, src) \
    asm volatile("cp.async.cg.shared.global [%0], [%1], 16;" :: "r"(dst), "l"(src) : "memory")
#define CP_COMMIT()  asm volatile("cp.async.commit_group;" ::: "memory")
#define CP_WAIT1()   asm volatile("cp.async.wait_group 1;" ::: "memory")
#define CP_WAIT0()   asm volatile("cp.async.wait_group 0;" ::: "memory")

__device__ __forceinline__ uint32_t smem_u32(const void* p) {
    uint32_t a;
    asm("{ .reg .u64 t; cvta.to.shared.u64 t, %1; cvt.u32.u64 %0, t; }" : "=r"(a) : "l"(p));
    return a;
}

#define LDSM_X4(r0, r1, r2, r3, addr)                                        \
    asm volatile("ldmatrix.sync.aligned.m8n8.x4.shared.b16 {%0,%1,%2,%3}, [%4];" \
        : "=r"(r0), "=r"(r1), "=r"(r2), "=r"(r3) : "r"(addr))

#define LDSM_X4T(r0, r1, r2, r3, addr)                                       \
    asm volatile("ldmatrix.sync.aligned.m8n8.x4.trans.shared.b16 {%0,%1,%2,%3}, [%4];" \
        : "=r"(r0), "=r"(r1), "=r"(r2), "=r"(r3) : "r"(addr))

// m16n8k16 fp16 mma, fp32 accum
__device__ __forceinline__ void mma_f16(
    float& c0, float& c1, float& c2, float& c3,
    uint32_t a0, uint32_t a1, uint32_t a2, uint32_t a3,
    uint32_t b0, uint32_t b1)
{
    asm volatile(
        "mma.sync.aligned.m16n8k16.row.col.f32.f16.f16.f32 "
        "{%0,%1,%2,%3}, {%4,%5,%6,%7}, {%8,%9}, {%0,%1,%2,%3};"
        : "+f"(c0), "+f"(c1), "+f"(c2), "+f"(c3)
        : "r"(a0), "r"(a1), "r"(a2), "r"(a3), "r"(b0), "r"(b1));
}

// ---------------------------------------------------------------------------
// fp16 tensor GEMM (R7-proven): C[M,N] = A[M,K] @ Bm[N,K]^T.
// 128x128x64 block tile, 8 warps (2m x 4n) -> 64x32 warp tiles, 256 threads.
// A smem rows 144B; 3-stage cp.async; 2 CTAs/SM.
// TRV: B operand is V[t,d] row-major; tile [64 s x 128 d] with 272B rows,
//      consumed via ldmatrix.trans (B = V^T implicitly).
// TRI: 1D triangular grid decode (QK): idx -> (z, by desc, bx), 544 CTAs.
// EXPO: epilogue exp(acc*scale), causal mask on diag tile, rowsum atomics.
// DIVRS: divide by rs[row]. KLIM: causal K clip (heavy-first m order).
// CSKIP: skip fully-masked tiles (unused when TRI).
// ---------------------------------------------------------------------------
constexpr int BM = 128, BN = 128, BK = 64;
constexpr int LDHB = 144;                      // A/B(K-major) smem row bytes
constexpr int LDVB = 272;                      // TRV B smem row bytes (128 d)
constexpr int TILE_BYTES  = BM * LDHB;         // 18432
constexpr int STAGE_BYTES = 2 * TILE_BYTES;    // 36864 (TRV B fits: 64*272=17408)
constexpr int NSTAGE = 3;
constexpr int SMEM_BYTES = NSTAGE * STAGE_BYTES;  // 110592

template <bool QKV3, bool BIAS, bool EXPO, bool DIVRS, bool CSKIP, bool KLIM, bool OUTH, bool TRV, bool TRI>
__global__ __launch_bounds__(256, 2) void gemm_h(
    const __half* __restrict__ A, const __half* __restrict__ Bm,
    const float* __restrict__ bias0, const float* __restrict__ bias1,
    const float* __restrict__ bias2, void* __restrict__ Cv,
    float* __restrict__ rs,
    int M, int N, int K, float scale, size_t sA, size_t sB, size_t sC)
{
    int z, by, bx;
    if (TRI) {
        const int idx = blockIdx.x;
        z = idx & 3;
        int rem = idx >> 2;                    // 0..135, heavy rows first
        by = 15;
        while (rem >= by + 1) { rem -= by + 1; by--; }
        bx = rem;
    } else {
        z = blockIdx.z;
        by = KLIM ? ((int)gridDim.y - 1 - (int)blockIdx.y) : (int)blockIdx.y;
        bx = blockIdx.x;
    }
    const int m0 = by * BM;
    const int n0 = bx * BN;
    if (CSKIP && !TRI && n0 >= m0 + BM) return;   // fully above causal diag

    A  += QKV3 ? 0 : (size_t)z * sA;
    Bm += (size_t)z * sB;
    const float* bias = bias0;
    if (QKV3) bias = (z == 0) ? bias0 : (z == 1) ? bias1 : bias2;

    int Keff = K;
    if (KLIM) { int lim = m0 + BM; Keff = lim < K ? lim : K; }
    const int KT = Keff / BK;

    extern __shared__ char sm[];
    const uint32_t sm_b = smem_u32(sm);

    const int tid = threadIdx.x;
    const int wid = tid >> 5;
    const int lid = tid & 31;
    const int wm = wid >> 2;                   // 0..1
    const int wn = wid & 3;                    // 0..3
    const int g  = lid >> 2;                   // 0..7
    const int t4 = lid & 3;                    // 0..3

    const __half* Ag = A + (size_t)m0 * K;
    const __half* Bg = TRV ? Bm : Bm + (size_t)n0 * K;

    // Stage loader: A 128x64h + B (K-major 128x64h | TRV 64s x 128d)
    auto load_stage = [&](int stage, int kt) {
        const uint32_t ab = sm_b + stage * STAGE_BYTES;
        const uint32_t bbs = ab + TILE_BYTES;
        const __half* Asrc = Ag + (size_t)kt * BK;
#pragma unroll
        for (int i = 0; i < 4; i++) {
            int idx = i * 256 + tid;           // 0..1023
            int row = idx >> 3, c = idx & 7;
            CP_ASYNC16(ab + (uint32_t)(row * LDHB + c * 16),
                       Asrc + (size_t)row * K + c * 8);
        }
        if (TRV) {
#pragma unroll
            for (int i = 0; i < 4; i++) {
                int idx = i * 256 + tid;       // 0..1023
                int r = idx >> 4, c = idx & 15;
                CP_ASYNC16(bbs + (uint32_t)(r * LDVB + c * 16),
                           Bg + (size_t)(kt * BK + r) * D_ + n0 + c * 8);
            }
        } else {
            const __half* Bsrc = Bg + (size_t)kt * BK;
#pragma unroll
            for (int i = 0; i < 4; i++) {
                int idx = i * 256 + tid;
                int row = idx >> 3, c = idx & 7;
                CP_ASYNC16(bbs + (uint32_t)(row * LDHB + c * 16),
                           Bsrc + (size_t)row * K + c * 8);
            }
        }
    };

    load_stage(0, 0);
    CP_COMMIT();
    if (KT > 1) { load_stage(1, 1); CP_COMMIT(); }

    // LDSM per-lane addresses.
    const int fr = lid & 15;
    const uint32_t lk = (lid & 16) ? 16u : 0u;
    const uint32_t aoff = (uint32_t)((wm * 64 + fr) * LDHB) + lk;
    const uint32_t boff = (uint32_t)(TILE_BYTES + (wn * 32 + fr) * LDHB) + lk;
    const int i8 = lid & 7;
    const int grp = lid >> 3;
    const uint32_t btrv = (uint32_t)(TILE_BYTES
                          + (((grp & 2) ? 8 : 0) + i8) * LDVB
                          + (wn * 32 + ((grp & 1) ? 8 : 0)) * 2);

    float acc[4][4][4];
#pragma unroll
    for (int i = 0; i < 4; i++)
#pragma unroll
        for (int j = 0; j < 4; j++)
#pragma unroll
            for (int r = 0; r < 4; r++) acc[i][j][r] = 0.f;

    int stage = 0;
    for (int kt = 0; kt < KT; kt++) {
        if (kt + 1 < KT) CP_WAIT1(); else CP_WAIT0();
        __syncthreads();

        if (kt + 2 < KT) {
            int ns = stage + 2; if (ns >= NSTAGE) ns -= NSTAGE;
            load_stage(ns, kt + 2);
            CP_COMMIT();
        }

        const uint32_t Sb = sm_b + stage * STAGE_BYTES;

#pragma unroll
        for (int s = 0; s < 4; s++) {          // 4 x k16 steps
            uint32_t a[4][4], b[2][4];
#pragma unroll
            for (int mt = 0; mt < 4; mt++)
                LDSM_X4(a[mt][0], a[mt][1], a[mt][2], a[mt][3],
                        Sb + aoff + mt * (16 * LDHB) + s * 32);
            if (TRV) {
#pragma unroll
                for (int p = 0; p < 2; p++)
                    LDSM_X4T(b[p][0], b[p][1], b[p][2], b[p][3],
                             Sb + btrv + s * (16 * LDVB) + p * 32);
            } else {
#pragma unroll
                for (int p = 0; p < 2; p++)
                    LDSM_X4(b[p][0], b[p][1], b[p][2], b[p][3],
                            Sb + boff + p * (16 * LDHB) + s * 32);
            }
#pragma unroll
            for (int mt = 0; mt < 4; mt++)
#pragma unroll
                for (int nt = 0; nt < 4; nt++) {
                    const int p = nt >> 1, o = nt & 1;
                    mma_f16(acc[mt][nt][0], acc[mt][nt][1],
                            acc[mt][nt][2], acc[mt][nt][3],
                            a[mt][0], a[mt][1], a[mt][2], a[mt][3],
                            b[p][o], b[p][2 + o]);
                }
        }
        stage++; if (stage >= NSTAGE) stage = 0;
    }

    const bool diag = EXPO && (m0 == n0);

    // Epilogue: c0,c1 -> (row g, cols 2t4,2t4+1); c2,c3 -> row g+8.
#pragma unroll
    for (int mt = 0; mt < 4; mt++) {
        const int mr = m0 + wm * 64 + mt * 16 + g;
        float rsum0 = 0.f, rsum1 = 0.f;
        float ia = 1.f, ib = 1.f;
        if (DIVRS) {
            ia = 1.0f / __ldg(rs + (size_t)z * T_ + mr);
            ib = 1.0f / __ldg(rs + (size_t)z * T_ + mr + 8);
        }
#pragma unroll
        for (int nt = 0; nt < 4; nt++) {
            const int nc = n0 + wn * 32 + nt * 8 + 2 * t4;
            float f0 = acc[mt][nt][0], f1 = acc[mt][nt][1];
            float f2 = acc[mt][nt][2], f3 = acc[mt][nt][3];
            if (BIAS) {
                float b0 = __ldg(bias + nc), b1 = __ldg(bias + nc + 1);
                f0 += b0; f1 += b1; f2 += b0; f3 += b1;
            }
            if (EXPO) {
                float e0 = __expf(f0 * scale), e1 = __expf(f1 * scale);
                float e2 = __expf(f2 * scale), e3 = __expf(f3 * scale);
                if (diag) {
                    if (nc     > mr    ) e0 = 0.f;
                    if (nc + 1 > mr    ) e1 = 0.f;
                    if (nc     > mr + 8) e2 = 0.f;
                    if (nc + 1 > mr + 8) e3 = 0.f;
                }
                __half2 h0 = __floats2half2_rn(e0, e1);
                __half2 h1 = __floats2half2_rn(e2, e3);
                float2 r0 = __half22float2(h0), r1 = __half22float2(h1);
                rsum0 += r0.x + r0.y;
                rsum1 += r1.x + r1.y;
                __half* C = (__half*)Cv + (size_t)z * sC;
                *(__half2*)(C + (size_t)mr * N + nc)       = h0;
                *(__half2*)(C + (size_t)(mr + 8) * N + nc) = h1;
            } else if (OUTH) {
                __half* C = (__half*)Cv + (size_t)z * sC;
                *(__half2*)(C + (size_t)mr * N + nc)       = __floats2half2_rn(f0, f1);
                *(__half2*)(C + (size_t)(mr + 8) * N + nc) = __floats2half2_rn(f2, f3);
            } else {
                if (DIVRS) { f0 *= ia; f1 *= ia; f2 *= ib; f3 *= ib; }
                float* C = (float*)Cv + (size_t)z * sC;
                *(float2*)(C + (size_t)mr * N + nc)       = make_float2(f0, f1);
                *(float2*)(C + (size_t)(mr + 8) * N + nc) = make_float2(f2, f3);
            }
        }
        if (EXPO) {
            rsum0 += __shfl_xor_sync(0xffffffffu, rsum0, 1);
            rsum0 += __shfl_xor_sync(0xffffffffu, rsum0, 2);
            rsum1 += __shfl_xor_sync(0xffffffffu, rsum1, 1);
            rsum1 += __shfl_xor_sync(0xffffffffu, rsum1, 2);
            if (t4 == 0) {
                atomicAdd(rs + (size_t)z * T_ + mr,     rsum0);
                atomicAdd(rs + (size_t)z * T_ + mr + 8, rsum1);
            }
        }
    }
}

// ---------------------------------------------------------------------------
// Fused prep: flat 1D grid.
//   blocks [0, 4096)        : x fp32 -> fp16 (8 floats/thread)
//   blocks [4096, 7168)     : W transposes (3 x 1024 blocks of 32x32 tiles)
//   blocks [7168, 7200)     : zero rs
// ---------------------------------------------------------------------------
__global__ __launch_bounds__(256) void prep_kernel(
    const float* __restrict__ x,
    const float* __restrict__ W0, const float* __restrict__ W1,
    const float* __restrict__ W2,
    __half* __restrict__ xh, __half* __restrict__ wt, float* __restrict__ rs)
{
    const int bid = blockIdx.x;
    const int tid = threadIdx.x;
    if (bid < 4096) {
        const int i = bid * 256 + tid;           // < 1048576
        float4 v0 = ((const float4*)x)[2 * i];
        float4 v1 = ((const float4*)x)[2 * i + 1];
        __half2 h[4];
        h[0] = __floats2half2_rn(v0.x, v0.y);
        h[1] = __floats2half2_rn(v0.z, v0.w);
        h[2] = __floats2half2_rn(v1.x, v1.y);
        h[3] = __floats2half2_rn(v1.z, v1.w);
        ((uint4*)xh)[i] = *(uint4*)h;
    } else if (bid < 7168) {
        const int b = bid - 4096;
        const int zz = b >> 10;                  // 0..2
        const int t = b & 1023;
        const int bx = t & 31, byy = t >> 5;     // 32x32 tile grid
        const float* src = (zz == 0) ? W0 : (zz == 1) ? W1 : W2;
        __half* d = wt + (size_t)zz * D_ * D_;
        __shared__ float tsh[32][33];
        const int tx = tid & 31, ty = tid >> 5;  // (32, 8)
        const int r0 = byy * 32, c0 = bx * 32;
#pragma unroll
        for (int i = 0; i < 4; i++) {
            int r = r0 + ty + i * 8;
            tsh[ty + i * 8][tx] = src[(size_t)r * D_ + c0 + tx];
        }
        __syncthreads();
#pragma unroll
        for (int i = 0; i < 4; i++) {
            int c = c0 + ty + i * 8;
            d[(size_t)c * D_ + r0 + tx] = __float2half_rn(tsh[tx][ty + i * 8]);
        }
    } else {
        const int i = (bid - 7168) * 256 + tid;
        if (i < B_ * T_) rs[i] = 0.f;
    }
}

// ---------------------------------------------------------------------------
extern "C" void kernel_launch(void* const* d_in, const int* in_sizes, int n_in,
                              void* d_out, int out_size)
{
    const float* x  = (const float*)d_in[0];
    const float* Wq = (const float*)d_in[1];
    const float* bq = (const float*)d_in[2];
    const float* Wk = (const float*)d_in[3];
    const float* bk = (const float*)d_in[4];
    const float* Wv = (const float*)d_in[5];
    const float* bv = (const float*)d_in[6];
    float* out = (float*)d_out;

    __half *xh, *wt, *qkv, *p;
    float *rs;
    cudaGetSymbolAddress((void**)&xh,  g_xh);
    cudaGetSymbolAddress((void**)&wt,  g_wt);
    cudaGetSymbolAddress((void**)&qkv, g_qkv);
    cudaGetSymbolAddress((void**)&p,   g_p);
    cudaGetSymbolAddress((void**)&rs,  g_rs);

    const int M = B_ * T_;               // 8192
    const size_t TD = (size_t)T_ * D_;
    const size_t TT = (size_t)T_ * T_;
    const size_t DD = (size_t)D_ * D_;
    __half* q = qkv;
    __half* k = qkv + (size_t)M * D_;
    __half* v = qkv + 2 * (size_t)M * D_;

    cudaFuncSetAttribute(gemm_h<true,  true,  false, false, false, false, true,  false, false>, cudaFuncAttributeMaxDynamicSharedMemorySize, SMEM_BYTES);
    cudaFuncSetAttribute(gemm_h<false, false, true,  false, false, false, true,  false, true >, cudaFuncAttributeMaxDynamicSharedMemorySize, SMEM_BYTES);
    cudaFuncSetAttribute(gemm_h<false, false, false, true,  false, true,  false, true,  false>, cudaFuncAttributeMaxDynamicSharedMemorySize, SMEM_BYTES);

    // 0) fused prep: x->fp16, W->W^T fp16, rs=0 (one launch)
    prep_kernel<<<7200, 256>>>(x, Wq, Wk, Wv, xh, wt, rs);

    // 1) fused QKV projections (one launch, z selects q/k/v), fp16 out
    dim3 gProj(D_ / BN, M / BM, 3);
    gemm_h<true, true, false, false, false, false, true, false, false><<<gProj, 256, SMEM_BYTES>>>(
        xh, wt, bq, bk, bv, qkv, nullptr, M, D_, D_, 1.f, 0, DD, (size_t)M * D_);

    // 2) E = exp(Q K^T / 32) fp16 — exact triangular 1D grid (544 CTAs,
    //    heavy rows first), diag masked, row sums via atomics.
    gemm_h<false, false, true, false, false, false, true, false, true><<<136 * 4, 256, SMEM_BYTES>>>(
        q, k, nullptr, nullptr, nullptr, p, rs, T_, T_, D_, 1.0f / 32.0f, TD, TD, TT);

    // 3) out = (E @ V) / rs, V via ldmatrix.trans (no v^T), causal K-limit,
    //    heavy-first m order, fp32 out
    dim3 gPV(D_ / BN, T_ / BM, B_);
    gemm_h<false, false, false, true, false, true, false, true, false><<<gPV, 256, SMEM_BYTES>>>(
        p, v, nullptr, nullptr, nullptr, out, rs, T_, D_, T_, 1.f, TT, TD, TD);
}

// round 14
// speedup vs baseline: 1.4609x; 1.0182x over previous
#include <cuda_runtime.h>
#include <cuda_fp16.h>
#include <cstdint>
#include <cstddef>

#define B_ 4
#define T_ 2048
#define D_ 1024

// ---------------------------------------------------------------------------
// Scratch (__device__ globals: allocation-free rule)
// ---------------------------------------------------------------------------
__device__ __half g_xh[(size_t)B_ * T_ * D_];           // x in fp16
__device__ __half g_wt[3][(size_t)D_ * D_];             // W^T fp16 (q,k,v)
__device__ __half g_qkv[3][(size_t)B_ * T_ * D_];       // q,k,v fp16
__device__ __half g_p [(size_t)B_ * T_ * T_];           // E = exp(S) fp16
__device__ float  g_rs[(size_t)B_ * T_];                // row sums of E

#define CP_ASYNC16(dst, src) \
    asm volatile("cp.async.cg.shared.global [%0], [%1], 16;" :: "r"(dst), "l"(src) : "memory")
#define CP_COMMIT()  asm volatile("cp.async.commit_group;" ::: "memory")
#define CP_WAIT1()   asm volatile("cp.async.wait_group 1;" ::: "memory")
#define CP_WAIT0()   asm volatile("cp.async.wait_group 0;" ::: "memory")

__device__ __forceinline__ uint32_t smem_u32(const void* p) {
    uint32_t a;
    asm("{ .reg .u64 t; cvta.to.shared.u64 t, %1; cvt.u32.u64 %0, t; }" : "=r"(a) : "l"(p));
    return a;
}

#define LDSM_X4(r0, r1, r2, r3, addr)                                        \
    asm volatile("ldmatrix.sync.aligned.m8n8.x4.shared.b16 {%0,%1,%2,%3}, [%4];" \
        : "=r"(r0), "=r"(r1), "=r"(r2), "=r"(r3) : "r"(addr))

#define LDSM_X4T(r0, r1, r2, r3, addr)                                       \
    asm volatile("ldmatrix.sync.aligned.m8n8.x4.trans.shared.b16 {%0,%1,%2,%3}, [%4];" \
        : "=r"(r0), "=r"(r1), "=r"(r2), "=r"(r3) : "r"(addr))

// m16n8k16 fp16 mma, fp32 accum
__device__ __forceinline__ void mma_f16(
    float& c0, float& c1, float& c2, float& c3,
    uint32_t a0, uint32_t a1, uint32_t a2, uint32_t a3,
    uint32_t b0, uint32_t b1)
{
    asm volatile(
        "mma.sync.aligned.m16n8k16.row.col.f32.f16.f16.f32 "
        "{%0,%1,%2,%3}, {%4,%5,%6,%7}, {%8,%9}, {%0,%1,%2,%3};"
        : "+f"(c0), "+f"(c1), "+f"(c2), "+f"(c3)
        : "r"(a0), "r"(a1), "r"(a2), "r"(a3), "r"(b0), "r"(b1));
}

// ---------------------------------------------------------------------------
// fp16 tensor GEMM (R7-proven core): C[M,N] = A[M,K] @ Bm[N,K]^T.
// 128x128x64 block tile, 8 warps (2m x 4n) -> 64x32 warp tiles, 256 threads.
// A smem rows 144B; 3-stage cp.async; 2 CTAs/SM.
// TRV: B operand is V[t,d] row-major; tile [64 s x 128 d], 272B rows,
//      consumed via ldmatrix.trans (B = V^T implicitly).
// TRI: 1D triangular decode (QK); NT tiles per CTA (idx = bid + t*gridDim.x).
// PAIR: PV complementary-row pairing: by = t ? blockIdx.y : 15-blockIdx.y
//       (constant total K work of 34 ktiles per CTA).
// EXPO: epilogue exp(acc*scale), causal mask on diag tile, rowsum atomics.
// DIVRS: divide by rs[row]. KLIM: causal K clip.
// ---------------------------------------------------------------------------
constexpr int BM = 128, BN = 128, BK = 64;
constexpr int LDHB = 144;                      // A/B(K-major) smem row bytes
constexpr int LDVB = 272;                      // TRV B smem row bytes (128 d)
constexpr int TILE_BYTES  = BM * LDHB;         // 18432
constexpr int STAGE_BYTES = 2 * TILE_BYTES;    // 36864 (TRV B fits: 64*272=17408)
constexpr int NSTAGE = 3;
constexpr int SMEM_BYTES = NSTAGE * STAGE_BYTES;  // 110592

template <bool QKV3, bool BIAS, bool EXPO, bool DIVRS, bool KLIM, bool OUTH,
          bool TRV, bool TRI, bool PAIR, int NT>
__global__ __launch_bounds__(256, 2) void gemm_h(
    const __half* __restrict__ Ain, const __half* __restrict__ Bin,
    const float* __restrict__ bias0, const float* __restrict__ bias1,
    const float* __restrict__ bias2, void* __restrict__ Cv,
    float* __restrict__ rs,
    int M, int N, int K, float scale, size_t sA, size_t sB, size_t sC)
{
    extern __shared__ char sm[];
    const uint32_t sm_b = smem_u32(sm);

    const int tid = threadIdx.x;
    const int wid = tid >> 5;
    const int lid = tid & 31;
    const int wm = wid >> 2;                   // 0..1
    const int wn = wid & 3;                    // 0..3
    const int g  = lid >> 2;                   // 0..7
    const int t4 = lid & 3;                    // 0..3

    // Tile-invariant LDSM per-lane addresses.
    const int fr = lid & 15;
    const uint32_t lk = (lid & 16) ? 16u : 0u;
    const uint32_t aoff = (uint32_t)((wm * 64 + fr) * LDHB) + lk;
    const uint32_t boff = (uint32_t)(TILE_BYTES + (wn * 32 + fr) * LDHB) + lk;
    const int i8 = lid & 7;
    const int grp = lid >> 3;
    const uint32_t btrv = (uint32_t)(TILE_BYTES
                          + (((grp & 2) ? 8 : 0) + i8) * LDVB
                          + (wn * 32 + ((grp & 1) ? 8 : 0)) * 2);

#pragma unroll 1
    for (int tt = 0; tt < NT; tt++) {
        int z, by, bx;
        if (TRI) {
            const int idx = blockIdx.x + tt * (int)gridDim.x;
            z = idx & 3;
            int rem = idx >> 2;                // 0..135, heavy rows first
            by = 15;
            while (rem >= by + 1) { rem -= by + 1; by--; }
            bx = rem;
        } else if (PAIR) {
            z = blockIdx.z;
            bx = blockIdx.x;
            by = tt ? (int)blockIdx.y : 15 - (int)blockIdx.y;
        } else {
            z = blockIdx.z;
            by = blockIdx.y;
            bx = blockIdx.x;
        }
        const int m0 = by * BM;
        const int n0 = bx * BN;

        const __half* A  = Ain + (QKV3 ? 0 : (size_t)z * sA);
        const __half* Bm = Bin + (size_t)z * sB;
        const float* bias = bias0;
        if (QKV3) bias = (z == 0) ? bias0 : (z == 1) ? bias1 : bias2;

        int Keff = K;
        if (KLIM) { int lim = m0 + BM; Keff = lim < K ? lim : K; }
        const int KT = Keff / BK;

        const __half* Ag = A + (size_t)m0 * K;
        const __half* Bg = TRV ? Bm : Bm + (size_t)n0 * K;

        auto load_stage = [&](int stage, int kt) {
            const uint32_t ab = sm_b + stage * STAGE_BYTES;
            const uint32_t bbs = ab + TILE_BYTES;
            const __half* Asrc = Ag + (size_t)kt * BK;
#pragma unroll
            for (int i = 0; i < 4; i++) {
                int idx = i * 256 + tid;       // 0..1023
                int row = idx >> 3, c = idx & 7;
                CP_ASYNC16(ab + (uint32_t)(row * LDHB + c * 16),
                           Asrc + (size_t)row * K + c * 8);
            }
            if (TRV) {
#pragma unroll
                for (int i = 0; i < 4; i++) {
                    int idx = i * 256 + tid;   // 0..1023
                    int r = idx >> 4, c = idx & 15;
                    CP_ASYNC16(bbs + (uint32_t)(r * LDVB + c * 16),
                               Bg + (size_t)(kt * BK + r) * D_ + n0 + c * 8);
                }
            } else {
                const __half* Bsrc = Bg + (size_t)kt * BK;
#pragma unroll
                for (int i = 0; i < 4; i++) {
                    int idx = i * 256 + tid;
                    int row = idx >> 3, c = idx & 7;
                    CP_ASYNC16(bbs + (uint32_t)(row * LDHB + c * 16),
                               Bsrc + (size_t)row * K + c * 8);
                }
            }
        };

        load_stage(0, 0);
        CP_COMMIT();
        if (KT > 1) { load_stage(1, 1); CP_COMMIT(); }

        float acc[4][4][4];
#pragma unroll
        for (int i = 0; i < 4; i++)
#pragma unroll
            for (int j = 0; j < 4; j++)
#pragma unroll
                for (int r = 0; r < 4; r++) acc[i][j][r] = 0.f;

        int stage = 0;
        for (int kt = 0; kt < KT; kt++) {
            if (kt + 1 < KT) CP_WAIT1(); else CP_WAIT0();
            __syncthreads();

            if (kt + 2 < KT) {
                int ns = stage + 2; if (ns >= NSTAGE) ns -= NSTAGE;
                load_stage(ns, kt + 2);
                CP_COMMIT();
            }

            const uint32_t Sb = sm_b + stage * STAGE_BYTES;

#pragma unroll
            for (int s = 0; s < 4; s++) {      // 4 x k16 steps
                uint32_t a[4][4], b[2][4];
#pragma unroll
                for (int mt = 0; mt < 4; mt++)
                    LDSM_X4(a[mt][0], a[mt][1], a[mt][2], a[mt][3],
                            Sb + aoff + mt * (16 * LDHB) + s * 32);
                if (TRV) {
#pragma unroll
                    for (int p = 0; p < 2; p++)
                        LDSM_X4T(b[p][0], b[p][1], b[p][2], b[p][3],
                                 Sb + btrv + s * (16 * LDVB) + p * 32);
                } else {
#pragma unroll
                    for (int p = 0; p < 2; p++)
                        LDSM_X4(b[p][0], b[p][1], b[p][2], b[p][3],
                                Sb + boff + p * (16 * LDHB) + s * 32);
                }
#pragma unroll
                for (int mt = 0; mt < 4; mt++)
#pragma unroll
                    for (int nt = 0; nt < 4; nt++) {
                        const int p = nt >> 1, o = nt & 1;
                        mma_f16(acc[mt][nt][0], acc[mt][nt][1],
                                acc[mt][nt][2], acc[mt][nt][3],
                                a[mt][0], a[mt][1], a[mt][2], a[mt][3],
                                b[p][o], b[p][2 + o]);
                    }
            }
            stage++; if (stage >= NSTAGE) stage = 0;
        }

        const bool diag = EXPO && (m0 == n0);

        // Epilogue: c0,c1 -> (row g, cols 2t4,2t4+1); c2,c3 -> row g+8.
#pragma unroll
        for (int mt = 0; mt < 4; mt++) {
            const int mr = m0 + wm * 64 + mt * 16 + g;
            float rsum0 = 0.f, rsum1 = 0.f;
            float ia = 1.f, ib = 1.f;
            if (DIVRS) {
                ia = 1.0f / __ldg(rs + (size_t)z * T_ + mr);
                ib = 1.0f / __ldg(rs + (size_t)z * T_ + mr + 8);
            }
#pragma unroll
            for (int nt = 0; nt < 4; nt++) {
                const int nc = n0 + wn * 32 + nt * 8 + 2 * t4;
                float f0 = acc[mt][nt][0], f1 = acc[mt][nt][1];
                float f2 = acc[mt][nt][2], f3 = acc[mt][nt][3];
                if (BIAS) {
                    float b0 = __ldg(bias + nc), b1 = __ldg(bias + nc + 1);
                    f0 += b0; f1 += b1; f2 += b0; f3 += b1;
                }
                if (EXPO) {
                    float e0 = __expf(f0 * scale), e1 = __expf(f1 * scale);
                    float e2 = __expf(f2 * scale), e3 = __expf(f3 * scale);
                    if (diag) {
                        if (nc     > mr    ) e0 = 0.f;
                        if (nc + 1 > mr    ) e1 = 0.f;
                        if (nc     > mr + 8) e2 = 0.f;
                        if (nc + 1 > mr + 8) e3 = 0.f;
                    }
                    __half2 h0 = __floats2half2_rn(e0, e1);
                    __half2 h1 = __floats2half2_rn(e2, e3);
                    float2 r0 = __half22float2(h0), r1 = __half22float2(h1);
                    rsum0 += r0.x + r0.y;
                    rsum1 += r1.x + r1.y;
                    __half* C = (__half*)Cv + (size_t)z * sC;
                    *(__half2*)(C + (size_t)mr * N + nc)       = h0;
                    *(__half2*)(C + (size_t)(mr + 8) * N + nc) = h1;
                } else if (OUTH) {
                    __half* C = (__half*)Cv + (size_t)z * sC;
                    *(__half2*)(C + (size_t)mr * N + nc)       = __floats2half2_rn(f0, f1);
                    *(__half2*)(C + (size_t)(mr + 8) * N + nc) = __floats2half2_rn(f2, f3);
                } else {
                    if (DIVRS) { f0 *= ia; f1 *= ia; f2 *= ib; f3 *= ib; }
                    float* C = (float*)Cv + (size_t)z * sC;
                    *(float2*)(C + (size_t)mr * N + nc)       = make_float2(f0, f1);
                    *(float2*)(C + (size_t)(mr + 8) * N + nc) = make_float2(f2, f3);
                }
            }
            if (EXPO) {
                rsum0 += __shfl_xor_sync(0xffffffffu, rsum0, 1);
                rsum0 += __shfl_xor_sync(0xffffffffu, rsum0, 2);
                rsum1 += __shfl_xor_sync(0xffffffffu, rsum1, 1);
                rsum1 += __shfl_xor_sync(0xffffffffu, rsum1, 2);
                if (t4 == 0) {
                    atomicAdd(rs + (size_t)z * T_ + mr,     rsum0);
                    atomicAdd(rs + (size_t)z * T_ + mr + 8, rsum1);
                }
            }
        }

        if (NT > 1 && tt + 1 < NT) __syncthreads();  // drain before smem reuse
    }
}

// ---------------------------------------------------------------------------
// Fused prep: flat 1D grid.
//   blocks [0, 4096)        : x fp32 -> fp16 (8 floats/thread)
//   blocks [4096, 7168)     : W transposes (3 x 1024 blocks of 32x32 tiles)
//   blocks [7168, 7200)     : zero rs
// ---------------------------------------------------------------------------
__global__ __launch_bounds__(256) void prep_kernel(
    const float* __restrict__ x,
    const float* __restrict__ W0, const float* __restrict__ W1,
    const float* __restrict__ W2,
    __half* __restrict__ xh, __half* __restrict__ wt, float* __restrict__ rs)
{
    const int bid = blockIdx.x;
    const int tid = threadIdx.x;
    if (bid < 4096) {
        const int i = bid * 256 + tid;           // < 1048576
        float4 v0 = ((const float4*)x)[2 * i];
        float4 v1 = ((const float4*)x)[2 * i + 1];
        __half2 h[4];
        h[0] = __floats2half2_rn(v0.x, v0.y);
        h[1] = __floats2half2_rn(v0.z, v0.w);
        h[2] = __floats2half2_rn(v1.x, v1.y);
        h[3] = __floats2half2_rn(v1.z, v1.w);
        ((uint4*)xh)[i] = *(uint4*)h;
    } else if (bid < 7168) {
        const int b = bid - 4096;
        const int zz = b >> 10;                  // 0..2
        const int t = b & 1023;
        const int bx = t & 31, byy = t >> 5;     // 32x32 tile grid
        const float* src = (zz == 0) ? W0 : (zz == 1) ? W1 : W2;
        __half* d = wt + (size_t)zz * D_ * D_;
        __shared__ float tsh[32][33];
        const int tx = tid & 31, ty = tid >> 5;  // (32, 8)
        const int r0 = byy * 32, c0 = bx * 32;
#pragma unroll
        for (int i = 0; i < 4; i++) {
            int r = r0 + ty + i * 8;
            tsh[ty + i * 8][tx] = src[(size_t)r * D_ + c0 + tx];
        }
        __syncthreads();
#pragma unroll
        for (int i = 0; i < 4; i++) {
            int c = c0 + ty + i * 8;
            d[(size_t)c * D_ + r0 + tx] = __float2half_rn(tsh[tx][ty + i * 8]);
        }
    } else {
        const int i = (bid - 7168) * 256 + tid;
        if (i < B_ * T_) rs[i] = 0.f;
    }
}

// ---------------------------------------------------------------------------
extern "C" void kernel_launch(void* const* d_in, const int* in_sizes, int n_in,
                              void* d_out, int out_size)
{
    const float* x  = (const float*)d_in[0];
    const float* Wq = (const float*)d_in[1];
    const float* bq = (const float*)d_in[2];
    const float* Wk = (const float*)d_in[3];
    const float* bk = (const float*)d_in[4];
    const float* Wv = (const float*)d_in[5];
    const float* bv = (const float*)d_in[6];
    float* out = (float*)d_out;

    __half *xh, *wt, *qkv, *p;
    float *rs;
    cudaGetSymbolAddress((void**)&xh,  g_xh);
    cudaGetSymbolAddress((void**)&wt,  g_wt);
    cudaGetSymbolAddress((void**)&qkv, g_qkv);
    cudaGetSymbolAddress((void**)&p,   g_p);
    cudaGetSymbolAddress((void**)&rs,  g_rs);

    const int M = B_ * T_;               // 8192
    const size_t TD = (size_t)T_ * D_;
    const size_t TT = (size_t)T_ * T_;
    const size_t DD = (size_t)D_ * D_;
    __half* q = qkv;
    __half* k = qkv + (size_t)M * D_;
    __half* v = qkv + 2 * (size_t)M * D_;

    cudaFuncSetAttribute(gemm_h<true,  true,  false, false, false, true,  false, false, false, 1>, cudaFuncAttributeMaxDynamicSharedMemorySize, SMEM_BYTES);
    cudaFuncSetAttribute(gemm_h<false, false, true,  false, false, true,  false, true,  false, 2>, cudaFuncAttributeMaxDynamicSharedMemorySize, SMEM_BYTES);
    cudaFuncSetAttribute(gemm_h<false, false, false, true,  true,  false, true,  false, true,  2>, cudaFuncAttributeMaxDynamicSharedMemorySize, SMEM_BYTES);

    // 0) fused prep: x->fp16, W->W^T fp16, rs=0 (one launch)
    prep_kernel<<<7200, 256>>>(x, Wq, Wk, Wv, xh, wt, rs);

    // 1) fused QKV projections (one launch, z selects q/k/v), fp16 out
    dim3 gProj(D_ / BN, M / BM, 3);
    gemm_h<true, true, false, false, false, true, false, false, false, 1><<<gProj, 256, SMEM_BYTES>>>(
        xh, wt, bq, bk, bv, qkv, nullptr, M, D_, D_, 1.f, 0, DD, (size_t)M * D_);

    // 2) E = exp(Q K^T / 32) fp16 — triangular decode, 272 CTAs x 2 tiles
    //    (single balanced wave), diag masked, row sums via atomics.
    gemm_h<false, false, true, false, false, true, false, true, false, 2><<<272, 256, SMEM_BYTES>>>(
        q, k, nullptr, nullptr, nullptr, p, rs, T_, T_, D_, 1.0f / 32.0f, TD, TD, TT);

    // 3) out = (E @ V) / rs, V via ldmatrix.trans; complementary-row pairing:
    //    256 CTAs x 2 tiles, constant 34 ktiles/CTA (one balanced wave).
    dim3 gPV(D_ / BN, 8, B_);
    gemm_h<false, false, false, true, true, false, true, false, true, 2><<<gPV, 256, SMEM_BYTES>>>(
        p, v, nullptr, nullptr, nullptr, out, rs, T_, D_, T_, 1.f, TT, TD, TD);
}

// round 15
// speedup vs baseline: 1.4697x; 1.0060x over previous
#include <cuda_runtime.h>
#include <cuda_fp16.h>
#include <cstdint>
#include <cstddef>

#define B_ 4
#define T_ 2048
#define D_ 1024

// ---------------------------------------------------------------------------
// Scratch (__device__ globals: allocation-free rule)
// ---------------------------------------------------------------------------
__device__ __half g_xh[(size_t)B_ * T_ * D_];           // x in fp16
__device__ __half g_wt[3][(size_t)D_ * D_];             // W^T fp16 (q,k,v)
__device__ __half g_qkv[3][(size_t)B_ * T_ * D_];       // q,k,v fp16
__device__ __half g_p [(size_t)B_ * T_ * T_];           // E = exp(S) fp16
__device__ float  g_rs[(size_t)B_ * T_];                // row sums of E
__device__ int    g_qctr[2];                            // tile queues (QK, PV)

#define CP_ASYNC16(dst, src) \
    asm volatile("cp.async.cg.shared.global [%0], [%1], 16;" :: "r"(dst), "l"(src) : "memory")
#define CP_COMMIT()  asm volatile("cp.async.commit_group;" ::: "memory")
#define CP_WAIT1()   asm volatile("cp.async.wait_group 1;" ::: "memory")
#define CP_WAIT0()   asm volatile("cp.async.wait_group 0;" ::: "memory")

__device__ __forceinline__ uint32_t smem_u32(const void* p) {
    uint32_t a;
    asm("{ .reg .u64 t; cvta.to.shared.u64 t, %1; cvt.u32.u64 %0, t; }" : "=r"(a) : "l"(p));
    return a;
}

#define LDSM_X4(r0, r1, r2, r3, addr)                                        \
    asm volatile("ldmatrix.sync.aligned.m8n8.x4.shared.b16 {%0,%1,%2,%3}, [%4];" \
        : "=r"(r0), "=r"(r1), "=r"(r2), "=r"(r3) : "r"(addr))

#define LDSM_X4T(r0, r1, r2, r3, addr)                                       \
    asm volatile("ldmatrix.sync.aligned.m8n8.x4.trans.shared.b16 {%0,%1,%2,%3}, [%4];" \
        : "=r"(r0), "=r"(r1), "=r"(r2), "=r"(r3) : "r"(addr))

// m16n8k16 fp16 mma, fp32 accum
__device__ __forceinline__ void mma_f16(
    float& c0, float& c1, float& c2, float& c3,
    uint32_t a0, uint32_t a1, uint32_t a2, uint32_t a3,
    uint32_t b0, uint32_t b1)
{
    asm volatile(
        "mma.sync.aligned.m16n8k16.row.col.f32.f16.f16.f32 "
        "{%0,%1,%2,%3}, {%4,%5,%6,%7}, {%8,%9}, {%0,%1,%2,%3};"
        : "+f"(c0), "+f"(c1), "+f"(c2), "+f"(c3)
        : "r"(a0), "r"(a1), "r"(a2), "r"(a3), "r"(b0), "r"(b1));
}

// ---------------------------------------------------------------------------
// fp16 tensor GEMM (R7-proven core): C[M,N] = A[M,K] @ Bm[N,K]^T.
// 128x128x64 block tile, 8 warps (2m x 4n) -> 64x32 warp tiles, 256 threads.
// A smem rows 144B; 3-stage cp.async; 2 CTAs/SM.
// TRV: B operand is V[t,d] row-major; tile [64 s x 128 d], 272B rows,
//      consumed via ldmatrix.trans (B = V^T implicitly).
// QMODE 0: static grid (QKV). QMODE 1: QK dynamic queue over 544 triangular
// tiles (heavy rows first). QMODE 2: PV dynamic queue over 512 tiles (heavy
// rows first, KT=(by+1)*2). Queues: pop-until-empty, no waiting.
// EXPO: epilogue exp(acc*scale), causal mask on diag tile, rowsum atomics.
// DIVRS: divide by rs[row]. KLIM: causal K clip.
// ---------------------------------------------------------------------------
constexpr int BM = 128, BN = 128, BK = 64;
constexpr int LDHB = 144;                      // A/B(K-major) smem row bytes
constexpr int LDVB = 272;                      // TRV B smem row bytes (128 d)
constexpr int TILE_BYTES  = BM * LDHB;         // 18432
constexpr int STAGE_BYTES = 2 * TILE_BYTES;    // 36864 (TRV B fits: 64*272=17408)
constexpr int NSTAGE = 3;
constexpr int SMEM_BYTES = NSTAGE * STAGE_BYTES;  // 110592
constexpr int NQK_TILES = 136 * 4;             // 544
constexpr int NPV_TILES = 512;
constexpr int NWORKERS  = 296;                 // 2 CTAs x 148 SMs

template <bool QKV3, bool BIAS, bool EXPO, bool DIVRS, bool KLIM, bool OUTH,
          bool TRV, int QMODE>
__global__ __launch_bounds__(256, 2) void gemm_h(
    const __half* __restrict__ Ain, const __half* __restrict__ Bin,
    const float* __restrict__ bias0, const float* __restrict__ bias1,
    const float* __restrict__ bias2, void* __restrict__ Cv,
    float* __restrict__ rs, int* __restrict__ qctr,
    int M, int N, int K, float scale, size_t sA, size_t sB, size_t sC)
{
    extern __shared__ char sm[];
    const uint32_t sm_b = smem_u32(sm);
    __shared__ int sm_idx;

    const int tid = threadIdx.x;
    const int wid = tid >> 5;
    const int lid = tid & 31;
    const int wm = wid >> 2;                   // 0..1
    const int wn = wid & 3;                    // 0..3
    const int g  = lid >> 2;                   // 0..7
    const int t4 = lid & 3;                    // 0..3

    // Tile-invariant LDSM per-lane addresses.
    const int fr = lid & 15;
    const uint32_t lk = (lid & 16) ? 16u : 0u;
    const uint32_t aoff = (uint32_t)((wm * 64 + fr) * LDHB) + lk;
    const uint32_t boff = (uint32_t)(TILE_BYTES + (wn * 32 + fr) * LDHB) + lk;
    const int i8 = lid & 7;
    const int grp = lid >> 3;
    const uint32_t btrv = (uint32_t)(TILE_BYTES
                          + (((grp & 2) ? 8 : 0) + i8) * LDVB
                          + (wn * 32 + ((grp & 1) ? 8 : 0)) * 2);

#pragma unroll 1
    for (int iter = 0; ; iter++) {
        int z, by, bx;
        if (QMODE == 0) {
            if (iter) break;
            z = blockIdx.z; by = blockIdx.y; bx = blockIdx.x;
        } else {
            if (tid == 0) sm_idx = atomicAdd(qctr, 1);
            __syncthreads();
            const int idx = sm_idx;
            const int ntot = (QMODE == 1) ? NQK_TILES : NPV_TILES;
            if (idx >= ntot) break;
            if (QMODE == 1) {
                z = idx & 3;
                int rem = idx >> 2;            // 0..135, heavy rows first
                by = 15;
                while (rem >= by + 1) { rem -= by + 1; by--; }
                bx = rem;
            } else {
                by = 15 - (idx >> 5);          // heavy rows first
                const int sub = idx & 31;
                z = sub >> 3;
                bx = sub & 7;
            }
        }
        const int m0 = by * BM;
        const int n0 = bx * BN;

        const __half* A  = Ain + (QKV3 ? 0 : (size_t)z * sA);
        const __half* Bm = Bin + (size_t)z * sB;
        const float* bias = bias0;
        if (QKV3) bias = (z == 0) ? bias0 : (z == 1) ? bias1 : bias2;

        int Keff = K;
        if (KLIM) { int lim = m0 + BM; Keff = lim < K ? lim : K; }
        const int KT = Keff / BK;

        const __half* Ag = A + (size_t)m0 * K;
        const __half* Bg = TRV ? Bm : Bm + (size_t)n0 * K;

        auto load_stage = [&](int stage, int kt) {
            const uint32_t ab = sm_b + stage * STAGE_BYTES;
            const uint32_t bbs = ab + TILE_BYTES;
            const __half* Asrc = Ag + (size_t)kt * BK;
#pragma unroll
            for (int i = 0; i < 4; i++) {
                int idx2 = i * 256 + tid;      // 0..1023
                int row = idx2 >> 3, c = idx2 & 7;
                CP_ASYNC16(ab + (uint32_t)(row * LDHB + c * 16),
                           Asrc + (size_t)row * K + c * 8);
            }
            if (TRV) {
#pragma unroll
                for (int i = 0; i < 4; i++) {
                    int idx2 = i * 256 + tid;  // 0..1023
                    int r = idx2 >> 4, c = idx2 & 15;
                    CP_ASYNC16(bbs + (uint32_t)(r * LDVB + c * 16),
                               Bg + (size_t)(kt * BK + r) * D_ + n0 + c * 8);
                }
            } else {
                const __half* Bsrc = Bg + (size_t)kt * BK;
#pragma unroll
                for (int i = 0; i < 4; i++) {
                    int idx2 = i * 256 + tid;
                    int row = idx2 >> 3, c = idx2 & 7;
                    CP_ASYNC16(bbs + (uint32_t)(row * LDHB + c * 16),
                               Bsrc + (size_t)row * K + c * 8);
                }
            }
        };

        load_stage(0, 0);
        CP_COMMIT();
        if (KT > 1) { load_stage(1, 1); CP_COMMIT(); }

        float acc[4][4][4];
#pragma unroll
        for (int i = 0; i < 4; i++)
#pragma unroll
            for (int j = 0; j < 4; j++)
#pragma unroll
                for (int r = 0; r < 4; r++) acc[i][j][r] = 0.f;

        int stage = 0;
        for (int kt = 0; kt < KT; kt++) {
            if (kt + 1 < KT) CP_WAIT1(); else CP_WAIT0();
            __syncthreads();

            if (kt + 2 < KT) {
                int ns = stage + 2; if (ns >= NSTAGE) ns -= NSTAGE;
                load_stage(ns, kt + 2);
                CP_COMMIT();
            }

            const uint32_t Sb = sm_b + stage * STAGE_BYTES;

#pragma unroll
            for (int s = 0; s < 4; s++) {      // 4 x k16 steps
                uint32_t a[4][4], b[2][4];
#pragma unroll
                for (int mt = 0; mt < 4; mt++)
                    LDSM_X4(a[mt][0], a[mt][1], a[mt][2], a[mt][3],
                            Sb + aoff + mt * (16 * LDHB) + s * 32);
                if (TRV) {
#pragma unroll
                    for (int p = 0; p < 2; p++)
                        LDSM_X4T(b[p][0], b[p][1], b[p][2], b[p][3],
                                 Sb + btrv + s * (16 * LDVB) + p * 32);
                } else {
#pragma unroll
                    for (int p = 0; p < 2; p++)
                        LDSM_X4(b[p][0], b[p][1], b[p][2], b[p][3],
                                Sb + boff + p * (16 * LDHB) + s * 32);
                }
#pragma unroll
                for (int mt = 0; mt < 4; mt++)
#pragma unroll
                    for (int nt = 0; nt < 4; nt++) {
                        const int p = nt >> 1, o = nt & 1;
                        mma_f16(acc[mt][nt][0], acc[mt][nt][1],
                                acc[mt][nt][2], acc[mt][nt][3],
                                a[mt][0], a[mt][1], a[mt][2], a[mt][3],
                                b[p][o], b[p][2 + o]);
                    }
            }
            stage++; if (stage >= NSTAGE) stage = 0;
        }

        const bool diag = EXPO && (m0 == n0);

        // Epilogue: c0,c1 -> (row g, cols 2t4,2t4+1); c2,c3 -> row g+8.
#pragma unroll
        for (int mt = 0; mt < 4; mt++) {
            const int mr = m0 + wm * 64 + mt * 16 + g;
            float rsum0 = 0.f, rsum1 = 0.f;
            float ia = 1.f, ib = 1.f;
            if (DIVRS) {
                ia = 1.0f / __ldg(rs + (size_t)z * T_ + mr);
                ib = 1.0f / __ldg(rs + (size_t)z * T_ + mr + 8);
            }
#pragma unroll
            for (int nt = 0; nt < 4; nt++) {
                const int nc = n0 + wn * 32 + nt * 8 + 2 * t4;
                float f0 = acc[mt][nt][0], f1 = acc[mt][nt][1];
                float f2 = acc[mt][nt][2], f3 = acc[mt][nt][3];
                if (BIAS) {
                    float b0 = __ldg(bias + nc), b1 = __ldg(bias + nc + 1);
                    f0 += b0; f1 += b1; f2 += b0; f3 += b1;
                }
                if (EXPO) {
                    float e0 = __expf(f0 * scale), e1 = __expf(f1 * scale);
                    float e2 = __expf(f2 * scale), e3 = __expf(f3 * scale);
                    if (diag) {
                        if (nc     > mr    ) e0 = 0.f;
                        if (nc + 1 > mr    ) e1 = 0.f;
                        if (nc     > mr + 8) e2 = 0.f;
                        if (nc + 1 > mr + 8) e3 = 0.f;
                    }
                    __half2 h0 = __floats2half2_rn(e0, e1);
                    __half2 h1 = __floats2half2_rn(e2, e3);
                    float2 r0 = __half22float2(h0), r1 = __half22float2(h1);
                    rsum0 += r0.x + r0.y;
                    rsum1 += r1.x + r1.y;
                    __half* C = (__half*)Cv + (size_t)z * sC;
                    *(__half2*)(C + (size_t)mr * N + nc)       = h0;
                    *(__half2*)(C + (size_t)(mr + 8) * N + nc) = h1;
                } else if (OUTH) {
                    __half* C = (__half*)Cv + (size_t)z * sC;
                    *(__half2*)(C + (size_t)mr * N + nc)       = __floats2half2_rn(f0, f1);
                    *(__half2*)(C + (size_t)(mr + 8) * N + nc) = __floats2half2_rn(f2, f3);
                } else {
                    if (DIVRS) { f0 *= ia; f1 *= ia; f2 *= ib; f3 *= ib; }
                    float* C = (float*)Cv + (size_t)z * sC;
                    *(float2*)(C + (size_t)mr * N + nc)       = make_float2(f0, f1);
                    *(float2*)(C + (size_t)(mr + 8) * N + nc) = make_float2(f2, f3);
                }
            }
            if (EXPO) {
                rsum0 += __shfl_xor_sync(0xffffffffu, rsum0, 1);
                rsum0 += __shfl_xor_sync(0xffffffffu, rsum0, 2);
                rsum1 += __shfl_xor_sync(0xffffffffu, rsum1, 1);
                rsum1 += __shfl_xor_sync(0xffffffffu, rsum1, 2);
                if (t4 == 0) {
                    atomicAdd(rs + (size_t)z * T_ + mr,     rsum0);
                    atomicAdd(rs + (size_t)z * T_ + mr + 8, rsum1);
                }
            }
        }

        if (QMODE != 0) __syncthreads();   // drain smem + guard sm_idx reuse
    }
}

// ---------------------------------------------------------------------------
// Fused prep: flat 1D grid.
//   blocks [0, 4096)        : x fp32 -> fp16 (8 floats/thread)
//   blocks [4096, 7168)     : W transposes (3 x 1024 blocks of 32x32 tiles)
//   blocks [7168, 7200)     : zero rs (+ tile-queue counters)
// ---------------------------------------------------------------------------
__global__ __launch_bounds__(256) void prep_kernel(
    const float* __restrict__ x,
    const float* __restrict__ W0, const float* __restrict__ W1,
    const float* __restrict__ W2,
    __half* __restrict__ xh, __half* __restrict__ wt, float* __restrict__ rs,
    int* __restrict__ qctr)
{
    const int bid = blockIdx.x;
    const int tid = threadIdx.x;
    if (bid < 4096) {
        const int i = bid * 256 + tid;           // < 1048576
        float4 v0 = ((const float4*)x)[2 * i];
        float4 v1 = ((const float4*)x)[2 * i + 1];
        __half2 h[4];
        h[0] = __floats2half2_rn(v0.x, v0.y);
        h[1] = __floats2half2_rn(v0.z, v0.w);
        h[2] = __floats2half2_rn(v1.x, v1.y);
        h[3] = __floats2half2_rn(v1.z, v1.w);
        ((uint4*)xh)[i] = *(uint4*)h;
    } else if (bid < 7168) {
        const int b = bid - 4096;
        const int zz = b >> 10;                  // 0..2
        const int t = b & 1023;
        const int bx = t & 31, byy = t >> 5;     // 32x32 tile grid
        const float* src = (zz == 0) ? W0 : (zz == 1) ? W1 : W2;
        __half* d = wt + (size_t)zz * D_ * D_;
        __shared__ float tsh[32][33];
        const int tx = tid & 31, ty = tid >> 5;  // (32, 8)
        const int r0 = byy * 32, c0 = bx * 32;
#pragma unroll
        for (int i = 0; i < 4; i++) {
            int r = r0 + ty + i * 8;
            tsh[ty + i * 8][tx] = src[(size_t)r * D_ + c0 + tx];
        }
        __syncthreads();
#pragma unroll
        for (int i = 0; i < 4; i++) {
            int c = c0 + ty + i * 8;
            d[(size_t)c * D_ + r0 + tx] = __float2half_rn(tsh[tx][ty + i * 8]);
        }
    } else {
        const int i = (bid - 7168) * 256 + tid;
        if (i < B_ * T_) rs[i] = 0.f;
        if (bid == 7168 && tid < 2) qctr[tid] = 0;
    }
}

// ---------------------------------------------------------------------------
extern "C" void kernel_launch(void* const* d_in, const int* in_sizes, int n_in,
                              void* d_out, int out_size)
{
    const float* x  = (const float*)d_in[0];
    const float* Wq = (const float*)d_in[1];
    const float* bq = (const float*)d_in[2];
    const float* Wk = (const float*)d_in[3];
    const float* bk = (const float*)d_in[4];
    const float* Wv = (const float*)d_in[5];
    const float* bv = (const float*)d_in[6];
    float* out = (float*)d_out;

    __half *xh, *wt, *qkv, *p;
    float *rs;
    int *qctr;
    cudaGetSymbolAddress((void**)&xh,  g_xh);
    cudaGetSymbolAddress((void**)&wt,  g_wt);
    cudaGetSymbolAddress((void**)&qkv, g_qkv);
    cudaGetSymbolAddress((void**)&p,   g_p);
    cudaGetSymbolAddress((void**)&rs,  g_rs);
    cudaGetSymbolAddress((void**)&qctr, g_qctr);

    const int M = B_ * T_;               // 8192
    const size_t TD = (size_t)T_ * D_;
    const size_t TT = (size_t)T_ * T_;
    const size_t DD = (size_t)D_ * D_;
    __half* q = qkv;
    __half* k = qkv + (size_t)M * D_;
    __half* v = qkv + 2 * (size_t)M * D_;

    cudaFuncSetAttribute(gemm_h<true,  true,  false, false, false, true,  false, 0>, cudaFuncAttributeMaxDynamicSharedMemorySize, SMEM_BYTES);
    cudaFuncSetAttribute(gemm_h<false, false, true,  false, false, true,  false, 1>, cudaFuncAttributeMaxDynamicSharedMemorySize, SMEM_BYTES);
    cudaFuncSetAttribute(gemm_h<false, false, false, true,  true,  false, true,  2>, cudaFuncAttributeMaxDynamicSharedMemorySize, SMEM_BYTES);

    // 0) fused prep: x->fp16, W->W^T fp16, rs=0, queues=0 (one launch)
    prep_kernel<<<7200, 256>>>(x, Wq, Wk, Wv, xh, wt, rs, qctr);

    // 1) fused QKV projections (one launch, z selects q/k/v), fp16 out
    dim3 gProj(D_ / BN, M / BM, 3);
    gemm_h<true, true, false, false, false, true, false, 0><<<gProj, 256, SMEM_BYTES>>>(
        xh, wt, bq, bk, bv, qkv, nullptr, nullptr, M, D_, D_, 1.f, 0, DD, (size_t)M * D_);

    // 2) E = exp(Q K^T / 32) fp16 — 296-worker dynamic queue over 544
    //    triangular tiles (heavy rows first), diag masked, rowsums via atomics.
    gemm_h<false, false, true, false, false, true, false, 1><<<NWORKERS, 256, SMEM_BYTES>>>(
        q, k, nullptr, nullptr, nullptr, p, rs, qctr, T_, T_, D_, 1.0f / 32.0f, TD, TD, TT);

    // 3) out = (E @ V) / rs — 296-worker dynamic queue over 512 tiles
    //    (heavy rows first), V via ldmatrix.trans, causal K-limit, fp32 out.
    gemm_h<false, false, false, true, true, false, true, 2><<<NWORKERS, 256, SMEM_BYTES>>>(
        p, v, nullptr, nullptr, nullptr, out, rs, qctr + 1, T_, D_, T_, 1.f, TT, TD, TD);
}

// round 16
// speedup vs baseline: 1.5062x; 1.0249x over previous
#include <cuda_runtime.h>
#include <cuda_fp16.h>
#include <cstdint>
#include <cstddef>

#define B_ 4
#define T_ 2048
#define D_ 1024

// ---------------------------------------------------------------------------
// Scratch (__device__ globals: allocation-free rule)
// ---------------------------------------------------------------------------
__device__ __half g_xh[(size_t)B_ * T_ * D_];           // x in fp16
__device__ __half g_wt[3][(size_t)D_ * D_];             // W^T fp16 (q,k,v)
__device__ __half g_qkv[3][(size_t)B_ * T_ * D_];       // q,k,v fp16
__device__ __half g_p [(size_t)B_ * T_ * T_];           // E = exp(S) fp16
__device__ float  g_rs[(size_t)B_ * T_];                // row sums of E
__device__ int    g_qctr[3];                            // tile queues (QKV, QK, PV)

#define CP_ASYNC16(dst, src) \
    asm volatile("cp.async.cg.shared.global [%0], [%1], 16;" :: "r"(dst), "l"(src) : "memory")
#define CP_COMMIT()  asm volatile("cp.async.commit_group;" ::: "memory")
#define CP_WAIT1()   asm volatile("cp.async.wait_group 1;" ::: "memory")
#define CP_WAIT0()   asm volatile("cp.async.wait_group 0;" ::: "memory")

__device__ __forceinline__ uint32_t smem_u32(const void* p) {
    uint32_t a;
    asm("{ .reg .u64 t; cvta.to.shared.u64 t, %1; cvt.u32.u64 %0, t; }" : "=r"(a) : "l"(p));
    return a;
}

#define LDSM_X4(r0, r1, r2, r3, addr)                                        \
    asm volatile("ldmatrix.sync.aligned.m8n8.x4.shared.b16 {%0,%1,%2,%3}, [%4];" \
        : "=r"(r0), "=r"(r1), "=r"(r2), "=r"(r3) : "r"(addr))

#define LDSM_X4T(r0, r1, r2, r3, addr)                                       \
    asm volatile("ldmatrix.sync.aligned.m8n8.x4.trans.shared.b16 {%0,%1,%2,%3}, [%4];" \
        : "=r"(r0), "=r"(r1), "=r"(r2), "=r"(r3) : "r"(addr))

// m16n8k16 fp16 mma, fp32 accum
__device__ __forceinline__ void mma_f16(
    float& c0, float& c1, float& c2, float& c3,
    uint32_t a0, uint32_t a1, uint32_t a2, uint32_t a3,
    uint32_t b0, uint32_t b1)
{
    asm volatile(
        "mma.sync.aligned.m16n8k16.row.col.f32.f16.f16.f32 "
        "{%0,%1,%2,%3}, {%4,%5,%6,%7}, {%8,%9}, {%0,%1,%2,%3};"
        : "+f"(c0), "+f"(c1), "+f"(c2), "+f"(c3)
        : "r"(a0), "r"(a1), "r"(a2), "r"(a3), "r"(b0), "r"(b1));
}

// ---------------------------------------------------------------------------
// Persistent-pipeline fp16 tensor GEMM. All variants queue-driven: 296
// workers pop tiles from a global counter; the cp.async group stream is
// continuous across tiles (next tile's first 2 stages prefetched in the
// current tile's last 2 load slots; epilogue overlaps their flight).
// QMODE 0: QKV (1536 tiles, z selects W/bias/out). QMODE 1: QK triangular
// (544 tiles, heavy rows first). QMODE 2: PV (512 tiles, heavy rows first,
// KT=(by+1)*2, V consumed via ldmatrix.trans).
// ---------------------------------------------------------------------------
constexpr int BM = 128, BN = 128, BK = 64;
constexpr int LDHB = 144;                      // A/B(K-major) smem row bytes
constexpr int LDVB = 272;                      // TRV B smem row bytes (128 d)
constexpr int TILE_BYTES  = BM * LDHB;         // 18432
constexpr int STAGE_BYTES = 2 * TILE_BYTES;    // 36864 (TRV B fits: 64*272=17408)
constexpr int NSTAGE = 3;
constexpr int SMEM_BYTES = NSTAGE * STAGE_BYTES;  // 110592
constexpr int NWORKERS  = 296;                 // 2 CTAs x 148 SMs

template <int QMODE>
__device__ __forceinline__ void decode_tile(int idx, int& z, int& by, int& bx)
{
    if (QMODE == 0) {                          // QKV: 8 x 64 x 3
        bx = idx & 7; by = (idx >> 3) & 63; z = idx >> 9;
    } else if (QMODE == 1) {                   // QK triangular, heavy first
        z = idx & 3;
        int rem = idx >> 2;
        by = 15;
        while (rem >= by + 1) { rem -= by + 1; by--; }
        bx = rem;
    } else {                                   // PV, heavy rows first
        by = 15 - (idx >> 5);
        const int sub = idx & 31;
        z = sub >> 3;
        bx = sub & 7;
    }
}

template <bool QKV3, bool BIAS, bool EXPO, bool DIVRS, bool KLIM, bool OUTH,
          bool TRV, int QMODE, int NTOT>
__global__ __launch_bounds__(256, 2) void gemm_h(
    const __half* __restrict__ Ain, const __half* __restrict__ Bin,
    const float* __restrict__ bias0, const float* __restrict__ bias1,
    const float* __restrict__ bias2, void* __restrict__ Cv,
    float* __restrict__ rs, int* __restrict__ qctr,
    int M, int N, int K, float scale, size_t sA, size_t sB, size_t sC)
{
    extern __shared__ char sm[];
    const uint32_t sm_b = smem_u32(sm);
    __shared__ int sm_idx;

    const int tid = threadIdx.x;
    const int wid = tid >> 5;
    const int lid = tid & 31;
    const int wm = wid >> 2;                   // 0..1
    const int wn = wid & 3;                    // 0..3
    const int g  = lid >> 2;                   // 0..7
    const int t4 = lid & 3;                    // 0..3

    // Tile-invariant LDSM per-lane addresses.
    const int fr = lid & 15;
    const uint32_t lk = (lid & 16) ? 16u : 0u;
    const uint32_t aoff = (uint32_t)((wm * 64 + fr) * LDHB) + lk;
    const uint32_t boff = (uint32_t)(TILE_BYTES + (wn * 32 + fr) * LDHB) + lk;
    const int i8 = lid & 7;
    const int grp = lid >> 3;
    const uint32_t btrv = (uint32_t)(TILE_BYTES
                          + (((grp & 2) ? 8 : 0) + i8) * LDVB
                          + (wn * 32 + ((grp & 1) ? 8 : 0)) * 2);

    // Issue one K-stage of loads for a tile given its base pointers.
    auto load_stage = [&](const __half* Ag, const __half* Bg, int n0,
                          int stage, int kt) {
        const uint32_t ab = sm_b + stage * STAGE_BYTES;
        const uint32_t bbs = ab + TILE_BYTES;
        const __half* Asrc = Ag + (size_t)kt * BK;
#pragma unroll
        for (int i = 0; i < 4; i++) {
            int idx2 = i * 256 + tid;          // 0..1023
            int row = idx2 >> 3, c = idx2 & 7;
            CP_ASYNC16(ab + (uint32_t)(row * LDHB + c * 16),
                       Asrc + (size_t)row * K + c * 8);
        }
        if (TRV) {
#pragma unroll
            for (int i = 0; i < 4; i++) {
                int idx2 = i * 256 + tid;      // 0..1023
                int r = idx2 >> 4, c = idx2 & 15;
                CP_ASYNC16(bbs + (uint32_t)(r * LDVB + c * 16),
                           Bg + (size_t)(kt * BK + r) * D_ + n0 + c * 8);
            }
        } else {
            const __half* Bsrc = Bg + (size_t)kt * BK;
#pragma unroll
            for (int i = 0; i < 4; i++) {
                int idx2 = i * 256 + tid;
                int row = idx2 >> 3, c = idx2 & 7;
                CP_ASYNC16(bbs + (uint32_t)(row * LDHB + c * 16),
                           Bsrc + (size_t)row * K + c * 8);
            }
        }
    };

    auto tile_ptrs = [&](int z, int m0, int n0, const __half*& Ag, const __half*& Bg) {
        const __half* A = Ain + (QKV3 ? 0 : (size_t)z * sA);
        Ag = A + (size_t)m0 * K;
        Bg = TRV ? Bin + (size_t)z * sB : Bin + (size_t)z * sB + (size_t)n0 * K;
    };
    auto tile_kt = [&](int m0) {
        int Keff = K;
        if (KLIM) { int lim = m0 + BM; Keff = lim < K ? lim : K; }
        return Keff / BK;
    };

    // --- first pop ---
    if (tid == 0) sm_idx = atomicAdd(qctr, 1);
    __syncthreads();
    int cidx = sm_idx;
    if (cidx >= NTOT) return;

    int cz, cby, cbx;
    decode_tile<QMODE>(cidx, cz, cby, cbx);
    int cm0 = cby * BM, cn0 = cbx * BN;
    const __half *cAg, *cBg;
    tile_ptrs(cz, cm0, cn0, cAg, cBg);
    int cKT = tile_kt(cm0);

    // next-tile state (lazily filled)
    int nz = 0, nm0 = 0, nn0 = 0, nKT = 0;
    const __half *nAg = nullptr, *nBg = nullptr;
    bool dead = false;

    // prologue: 2 groups (KT >= 2 always)
    load_stage(cAg, cBg, cn0, 0, 0); CP_COMMIT();
    load_stage(cAg, cBg, cn0, 1, 1); CP_COMMIT();

    float acc[4][4][4];
#pragma unroll
    for (int i = 0; i < 4; i++)
#pragma unroll
        for (int j = 0; j < 4; j++)
#pragma unroll
            for (int r = 0; r < 4; r++) acc[i][j][r] = 0.f;

    int stage = 0, ktl = 0;

#pragma unroll 1
    for (;;) {
        if (!dead) CP_WAIT1(); else CP_WAIT0();
        __syncthreads();

        // Issue exactly one load group (current tile k+2, or next tile's k0/k1).
        const int k2 = ktl + 2;
        int ls = stage + 2; if (ls >= NSTAGE) ls -= NSTAGE;
        if (k2 < cKT) {
            load_stage(cAg, cBg, cn0, ls, k2);
            CP_COMMIT();
        } else {
            if (k2 == cKT) {                   // pop next tile
                if (tid == 0) sm_idx = atomicAdd(qctr, 1);
                __syncthreads();
                const int ni = sm_idx;
                if (ni >= NTOT) dead = true;
                else {
                    int zz, yy, xx;
                    decode_tile<QMODE>(ni, zz, yy, xx);
                    nz = zz; nm0 = yy * BM; nn0 = xx * BN;
                    tile_ptrs(nz, nm0, nn0, nAg, nBg);
                    nKT = tile_kt(nm0);
                }
            }
            if (!dead) {
                load_stage(nAg, nBg, nn0, ls, k2 - cKT);
                CP_COMMIT();
            }
        }

        // Compute this K-stage.
        const uint32_t Sb = sm_b + stage * STAGE_BYTES;
#pragma unroll
        for (int s = 0; s < 4; s++) {          // 4 x k16 steps
            uint32_t a[4][4], b[2][4];
#pragma unroll
            for (int mt = 0; mt < 4; mt++)
                LDSM_X4(a[mt][0], a[mt][1], a[mt][2], a[mt][3],
                        Sb + aoff + mt * (16 * LDHB) + s * 32);
            if (TRV) {
#pragma unroll
                for (int p = 0; p < 2; p++)
                    LDSM_X4T(b[p][0], b[p][1], b[p][2], b[p][3],
                             Sb + btrv + s * (16 * LDVB) + p * 32);
            } else {
#pragma unroll
                for (int p = 0; p < 2; p++)
                    LDSM_X4(b[p][0], b[p][1], b[p][2], b[p][3],
                            Sb + boff + p * (16 * LDHB) + s * 32);
            }
#pragma unroll
            for (int mt = 0; mt < 4; mt++)
#pragma unroll
                for (int nt = 0; nt < 4; nt++) {
                    const int p = nt >> 1, o = nt & 1;
                    mma_f16(acc[mt][nt][0], acc[mt][nt][1],
                            acc[mt][nt][2], acc[mt][nt][3],
                            a[mt][0], a[mt][1], a[mt][2], a[mt][3],
                            b[p][o], b[p][2 + o]);
                }
        }
        ktl++;
        stage++; if (stage >= NSTAGE) stage = 0;

        if (ktl == cKT) {
            // Epilogue (registers only; next tile's loads already in flight).
            const float* bias = bias0;
            if (QKV3) bias = (cz == 0) ? bias0 : (cz == 1) ? bias1 : bias2;
            const bool diag = EXPO && (cm0 == cn0);
#pragma unroll
            for (int mt = 0; mt < 4; mt++) {
                const int mr = cm0 + wm * 64 + mt * 16 + g;
                float rsum0 = 0.f, rsum1 = 0.f;
                float ia = 1.f, ib = 1.f;
                if (DIVRS) {
                    ia = 1.0f / __ldg(rs + (size_t)cz * T_ + mr);
                    ib = 1.0f / __ldg(rs + (size_t)cz * T_ + mr + 8);
                }
#pragma unroll
                for (int nt = 0; nt < 4; nt++) {
                    const int nc = cn0 + wn * 32 + nt * 8 + 2 * t4;
                    float f0 = acc[mt][nt][0], f1 = acc[mt][nt][1];
                    float f2 = acc[mt][nt][2], f3 = acc[mt][nt][3];
                    if (BIAS) {
                        float b0 = __ldg(bias + nc), b1 = __ldg(bias + nc + 1);
                        f0 += b0; f1 += b1; f2 += b0; f3 += b1;
                    }
                    if (EXPO) {
                        float e0 = __expf(f0 * scale), e1 = __expf(f1 * scale);
                        float e2 = __expf(f2 * scale), e3 = __expf(f3 * scale);
                        if (diag) {
                            if (nc     > mr    ) e0 = 0.f;
                            if (nc + 1 > mr    ) e1 = 0.f;
                            if (nc     > mr + 8) e2 = 0.f;
                            if (nc + 1 > mr + 8) e3 = 0.f;
                        }
                        __half2 h0 = __floats2half2_rn(e0, e1);
                        __half2 h1 = __floats2half2_rn(e2, e3);
                        float2 r0 = __half22float2(h0), r1 = __half22float2(h1);
                        rsum0 += r0.x + r0.y;
                        rsum1 += r1.x + r1.y;
                        __half* C = (__half*)Cv + (size_t)cz * sC;
                        *(__half2*)(C + (size_t)mr * N + nc)       = h0;
                        *(__half2*)(C + (size_t)(mr + 8) * N + nc) = h1;
                    } else if (OUTH) {
                        __half* C = (__half*)Cv + (size_t)cz * sC;
                        *(__half2*)(C + (size_t)mr * N + nc)       = __floats2half2_rn(f0, f1);
                        *(__half2*)(C + (size_t)(mr + 8) * N + nc) = __floats2half2_rn(f2, f3);
                    } else {
                        if (DIVRS) { f0 *= ia; f1 *= ia; f2 *= ib; f3 *= ib; }
                        float* C = (float*)Cv + (size_t)cz * sC;
                        *(float2*)(C + (size_t)mr * N + nc)       = make_float2(f0, f1);
                        *(float2*)(C + (size_t)(mr + 8) * N + nc) = make_float2(f2, f3);
                    }
                }
                if (EXPO) {
                    rsum0 += __shfl_xor_sync(0xffffffffu, rsum0, 1);
                    rsum0 += __shfl_xor_sync(0xffffffffu, rsum0, 2);
                    rsum1 += __shfl_xor_sync(0xffffffffu, rsum1, 1);
                    rsum1 += __shfl_xor_sync(0xffffffffu, rsum1, 2);
                    if (t4 == 0) {
                        atomicAdd(rs + (size_t)cz * T_ + mr,     rsum0);
                        atomicAdd(rs + (size_t)cz * T_ + mr + 8, rsum1);
                    }
                }
            }
            if (dead) break;
            // swap to next tile (its k0/k1 already in flight)
            cz = nz; cm0 = nm0; cn0 = nn0; cAg = nAg; cBg = nBg; cKT = nKT;
            ktl = 0;
#pragma unroll
            for (int i = 0; i < 4; i++)
#pragma unroll
                for (int j = 0; j < 4; j++)
#pragma unroll
                    for (int r = 0; r < 4; r++) acc[i][j][r] = 0.f;
        }
    }
}

// ---------------------------------------------------------------------------
// Fused prep: flat 1D grid.
//   blocks [0, 4096)        : x fp32 -> fp16 (8 floats/thread)
//   blocks [4096, 7168)     : W transposes (3 x 1024 blocks of 32x32 tiles)
//   blocks [7168, 7200)     : zero rs (+ tile-queue counters)
// ---------------------------------------------------------------------------
__global__ __launch_bounds__(256) void prep_kernel(
    const float* __restrict__ x,
    const float* __restrict__ W0, const float* __restrict__ W1,
    const float* __restrict__ W2,
    __half* __restrict__ xh, __half* __restrict__ wt, float* __restrict__ rs,
    int* __restrict__ qctr)
{
    const int bid = blockIdx.x;
    const int tid = threadIdx.x;
    if (bid < 4096) {
        const int i = bid * 256 + tid;           // < 1048576
        float4 v0 = ((const float4*)x)[2 * i];
        float4 v1 = ((const float4*)x)[2 * i + 1];
        __half2 h[4];
        h[0] = __floats2half2_rn(v0.x, v0.y);
        h[1] = __floats2half2_rn(v0.z, v0.w);
        h[2] = __floats2half2_rn(v1.x, v1.y);
        h[3] = __floats2half2_rn(v1.z, v1.w);
        ((uint4*)xh)[i] = *(uint4*)h;
    } else if (bid < 7168) {
        const int b = bid - 4096;
        const int zz = b >> 10;                  // 0..2
        const int t = b & 1023;
        const int bx = t & 31, byy = t >> 5;     // 32x32 tile grid
        const float* src = (zz == 0) ? W0 : (zz == 1) ? W1 : W2;
        __half* d = wt + (size_t)zz * D_ * D_;
        __shared__ float tsh[32][33];
        const int tx = tid & 31, ty = tid >> 5;  // (32, 8)
        const int r0 = byy * 32, c0 = bx * 32;
#pragma unroll
        for (int i = 0; i < 4; i++) {
            int r = r0 + ty + i * 8;
            tsh[ty + i * 8][tx] = src[(size_t)r * D_ + c0 + tx];
        }
        __syncthreads();
#pragma unroll
        for (int i = 0; i < 4; i++) {
            int c = c0 + ty + i * 8;
            d[(size_t)c * D_ + r0 + tx] = __float2half_rn(tsh[tx][ty + i * 8]);
        }
    } else {
        const int i = (bid - 7168) * 256 + tid;
        if (i < B_ * T_) rs[i] = 0.f;
        if (bid == 7168 && tid < 3) qctr[tid] = 0;
    }
}

// ---------------------------------------------------------------------------
extern "C" void kernel_launch(void* const* d_in, const int* in_sizes, int n_in,
                              void* d_out, int out_size)
{
    const float* x  = (const float*)d_in[0];
    const float* Wq = (const float*)d_in[1];
    const float* bq = (const float*)d_in[2];
    const float* Wk = (const float*)d_in[3];
    const float* bk = (const float*)d_in[4];
    const float* Wv = (const float*)d_in[5];
    const float* bv = (const float*)d_in[6];
    float* out = (float*)d_out;

    __half *xh, *wt, *qkv, *p;
    float *rs;
    int *qctr;
    cudaGetSymbolAddress((void**)&xh,  g_xh);
    cudaGetSymbolAddress((void**)&wt,  g_wt);
    cudaGetSymbolAddress((void**)&qkv, g_qkv);
    cudaGetSymbolAddress((void**)&p,   g_p);
    cudaGetSymbolAddress((void**)&rs,  g_rs);
    cudaGetSymbolAddress((void**)&qctr, g_qctr);

    const int M = B_ * T_;               // 8192
    const size_t TD = (size_t)T_ * D_;
    const size_t TT = (size_t)T_ * T_;
    const size_t DD = (size_t)D_ * D_;
    __half* q = qkv;
    __half* k = qkv + (size_t)M * D_;
    __half* v = qkv + 2 * (size_t)M * D_;

    cudaFuncSetAttribute(gemm_h<true,  true,  false, false, false, true,  false, 0, 1536>, cudaFuncAttributeMaxDynamicSharedMemorySize, SMEM_BYTES);
    cudaFuncSetAttribute(gemm_h<false, false, true,  false, false, true,  false, 1, 544>,  cudaFuncAttributeMaxDynamicSharedMemorySize, SMEM_BYTES);
    cudaFuncSetAttribute(gemm_h<false, false, false, true,  true,  false, true,  2, 512>,  cudaFuncAttributeMaxDynamicSharedMemorySize, SMEM_BYTES);

    // 0) fused prep: x->fp16, W->W^T fp16, rs=0, queues=0 (one launch)
    prep_kernel<<<7200, 256>>>(x, Wq, Wk, Wv, xh, wt, rs, qctr);

    // 1) QKV projections — persistent pipeline over 1536 tiles
    gemm_h<true, true, false, false, false, true, false, 0, 1536><<<NWORKERS, 256, SMEM_BYTES>>>(
        xh, wt, bq, bk, bv, qkv, nullptr, qctr + 2, M, D_, D_, 1.f, 0, DD, (size_t)M * D_);

    // 2) E = exp(Q K^T / 32) fp16 — persistent pipeline over 544 triangular
    //    tiles (heavy rows first), diag masked, rowsums via atomics.
    gemm_h<false, false, true, false, false, true, false, 1, 544><<<NWORKERS, 256, SMEM_BYTES>>>(
        q, k, nullptr, nullptr, nullptr, p, rs, qctr, T_, T_, D_, 1.0f / 32.0f, TD, TD, TT);

    // 3) out = (E @ V) / rs — persistent pipeline over 512 tiles (heavy rows
    //    first), V via ldmatrix.trans, causal K-limit, fp32 out.
    gemm_h<false, false, false, true, true, false, true, 2, 512><<<NWORKERS, 256, SMEM_BYTES>>>(
        p, v, nullptr, nullptr, nullptr, out, rs, qctr + 1, T_, D_, T_, 1.f, TT, TD, TD);
}